// round 4
// baseline (speedup 1.0000x reference)
#include <cuda_runtime.h>
#include <math.h>

#define DH 256          // feature dim (D == H == 256)
#define AOUT 8
#define MAXN 20000
#define MAXE 320000
#define MAXT (MAXN + MAXE)

// ---------------- device scratch (no allocations allowed) ----------------
__device__ float    g_bufA[(size_t)MAXN * DH];
__device__ float    g_bufB[(size_t)MAXN * DH];
__device__ float    g_obsr[(size_t)MAXN * DH];   // tf32-rounded obs
__device__ float    g_w1r[DH * DH];
__device__ float    g_w2r[DH * DH];
__device__ float    g_wm1r[DH * DH];
__device__ float    g_as1[MAXN];
__device__ float    g_ad1[MAXN];
__device__ float    g_as2[MAXN];
__device__ float    g_ad2[MAXN];
__device__ int      g_rowptr[MAXN + 1];
__device__ int      g_cursor[MAXN];
__device__ int      g_perm[MAXT];       // src node ids grouped by dst

__device__ __forceinline__ float rnd_tf32(float x) {
    unsigned u;
    asm("cvt.rna.tf32.f32 %0, %1;" : "=r"(u) : "f"(x));
    return __uint_as_float(u);
}

// ---------------- prep: round inputs to tf32, zero cursors + score accs ----------------
__global__ void k_prep(const float* __restrict__ obs,
                       const float* __restrict__ W1,
                       const float* __restrict__ W2,
                       const float* __restrict__ Wm1, int N)
{
    int nobs = N * DH;
    int i = blockIdx.x * blockDim.x + threadIdx.x;
    if (i < nobs) {
        g_obsr[i] = rnd_tf32(obs[i]);
    } else if (i < nobs + 65536) {
        int j = i - nobs;
        g_w1r[j] = rnd_tf32(W1[j]);
    } else if (i < nobs + 2 * 65536) {
        int j = i - nobs - 65536;
        g_w2r[j] = rnd_tf32(W2[j]);
    } else if (i < nobs + 3 * 65536) {
        int j = i - nobs - 2 * 65536;
        g_wm1r[j] = rnd_tf32(Wm1[j]);
    } else {
        int j = i - nobs - 3 * 65536;
        if (j < N) {
            g_cursor[j] = 0;
            g_as1[j] = 0.f; g_ad1[j] = 0.f;
            g_as2[j] = 0.f; g_ad2[j] = 0.f;
        }
    }
}

// ---------------- CSR build (self-loops handled implicitly) ----------------
__global__ void k_count(const int* __restrict__ ei, int E) {
    int q = blockIdx.x * blockDim.x + threadIdx.x;
    if (q * 4 >= E) return;
    int4 d4 = *(const int4*)(ei + E + q * 4);
    atomicAdd(&g_cursor[d4.x], 1);
    atomicAdd(&g_cursor[d4.y], 1);
    atomicAdd(&g_cursor[d4.z], 1);
    atomicAdd(&g_cursor[d4.w], 1);
}

__global__ void k_scan(int N) {
    __shared__ int sh[1024];
    int tid = threadIdx.x;
    int per = (N + 1023) >> 10;
    int b0 = tid * per;
    int b1 = min(b0 + per, N);
    int loc = 0;
    for (int i = b0; i < b1; i++) loc += g_cursor[i] + 1;   // +1 self-loop
    sh[tid] = loc;
    __syncthreads();
#pragma unroll
    for (int o = 1; o < 1024; o <<= 1) {
        int t = (tid >= o) ? sh[tid - o] : 0;
        __syncthreads();
        sh[tid] += t;
        __syncthreads();
    }
    int run = (tid == 0) ? 0 : sh[tid - 1];
    for (int i = b0; i < b1; i++) {
        int c = g_cursor[i] + 1;
        g_rowptr[i] = run;
        g_perm[run] = i;            // self-loop at group head, no atomic
        g_cursor[i] = run + 1;
        run += c;
    }
    if (tid == 1023) g_rowptr[N] = sh[1023];
}

__global__ void k_scatter(const int* __restrict__ ei, int E) {
    int e = blockIdx.x * blockDim.x + threadIdx.x;
    if (e >= E) return;
    int s = ei[e], d = ei[E + e];
    int pos = atomicAdd(&g_cursor[d], 1);
    g_perm[pos] = s;
}

// ---------------- tf32 tensor-core GEMM: C[M,256] = A[M,256] @ B[256,256] ----------------
// CTA 128x128, BK=16, 8 warps (each 32x64), 3-stage cp.async pipeline, 2 CTAs/SM.
#define GBM 128
#define GBN 128
#define GBK 16
#define ASTR 20     // 16 + 4 pad (conflict-free mod 32)
#define BSTR 136    // 128 + 8 pad (conflict-free mod 32)
#define ASZ (GBM * ASTR)     // 2560
#define BSZ (GBK * BSTR)     // 2176
#define NSTAGE 3
#define SMEM_GEMM ((NSTAGE * (ASZ + BSZ)) * 4)   // 56832 bytes

__global__ __launch_bounds__(256, 2) void k_gemm_tf32(
    const float* __restrict__ A, const float* __restrict__ B,
    float* __restrict__ C, int M,
    const float* __restrict__ bias, int act,
    const float* __restrict__ asrc, const float* __restrict__ adst,
    float* as_out, float* ad_out)
{
    extern __shared__ float sm[];
    float* As = sm;                    // [NSTAGE][GBM][ASTR]
    float* Bs = sm + NSTAGE * ASZ;     // [NSTAGE][GBK][BSTR]

    const int tid = threadIdx.x;
    const int warpId = tid >> 5, lane = tid & 31;
    const int gid = lane >> 2, tg = lane & 3;
    const int wm = warpId >> 1, wn = warpId & 1;    // 4x2 warp grid
    const int rowBlk = blockIdx.y * GBM;
    const int colBlk = blockIdx.x * GBN;

    float c[2][8][4];
#pragma unroll
    for (int mt = 0; mt < 2; mt++)
#pragma unroll
        for (int nt = 0; nt < 8; nt++)
#pragma unroll
            for (int q = 0; q < 4; q++) c[mt][nt][q] = 0.f;

    auto issue = [&](int buf, int k0) {
#pragma unroll
        for (int i = 0; i < 2; i++) {           // A: 128x16 = 512 float4
            int f = tid + i * 256;
            int r = f >> 2, kq = (f & 3) << 2;
            int grow = rowBlk + r;
            const float* src = A + (size_t)grow * DH + k0 + kq;
            unsigned dst = (unsigned)__cvta_generic_to_shared(&As[buf * ASZ + r * ASTR + kq]);
            int sz = (grow < M) ? 16 : 0;
            asm volatile("cp.async.cg.shared.global [%0], [%1], 16, %2;\n"
                         :: "r"(dst), "l"(src), "r"(sz));
        }
#pragma unroll
        for (int i = 0; i < 2; i++) {           // B: 16x128 = 512 float4
            int f = tid + i * 256;
            int kr = f >> 5, nq = (f & 31) << 2;
            const float* src = B + (size_t)(k0 + kr) * DH + colBlk + nq;
            unsigned dst = (unsigned)__cvta_generic_to_shared(&Bs[buf * BSZ + kr * BSTR + nq]);
            asm volatile("cp.async.cg.shared.global [%0], [%1], 16;\n"
                         :: "r"(dst), "l"(src));
        }
        asm volatile("cp.async.commit_group;\n");
    };

    auto compute = [&](int buf) {
#pragma unroll
        for (int ks = 0; ks < 2; ks++) {
            const int kk = ks * 8;
            float a[2][4], b[8][2];
#pragma unroll
            for (int mt = 0; mt < 2; mt++) {
                const float* ab = &As[buf * ASZ + (wm * 32 + mt * 16 + gid) * ASTR + kk + tg];
                a[mt][0] = ab[0];
                a[mt][1] = ab[8 * ASTR];
                a[mt][2] = ab[4];
                a[mt][3] = ab[8 * ASTR + 4];
            }
#pragma unroll
            for (int nt = 0; nt < 8; nt++) {
                const float* bb = &Bs[buf * BSZ + (kk + tg) * BSTR + wn * 64 + nt * 8 + gid];
                b[nt][0] = bb[0];
                b[nt][1] = bb[4 * BSTR];
            }
#pragma unroll
            for (int mt = 0; mt < 2; mt++)
#pragma unroll
                for (int nt = 0; nt < 8; nt++) {
                    asm volatile(
                        "mma.sync.aligned.m16n8k8.row.col.f32.tf32.tf32.f32 "
                        "{%0,%1,%2,%3}, {%4,%5,%6,%7}, {%8,%9}, {%0,%1,%2,%3};\n"
                        : "+f"(c[mt][nt][0]), "+f"(c[mt][nt][1]),
                          "+f"(c[mt][nt][2]), "+f"(c[mt][nt][3])
                        : "r"(__float_as_uint(a[mt][0])), "r"(__float_as_uint(a[mt][1])),
                          "r"(__float_as_uint(a[mt][2])), "r"(__float_as_uint(a[mt][3])),
                          "r"(__float_as_uint(b[nt][0])), "r"(__float_as_uint(b[nt][1])));
                }
        }
    };

    issue(0, 0);
    issue(1, GBK);
#pragma unroll
    for (int it = 0; it < DH / GBK; it++) {
        if (it < DH / GBK - 1)
            asm volatile("cp.async.wait_group 1;\n");
        else
            asm volatile("cp.async.wait_group 0;\n");
        __syncthreads();
        if (it + 2 < DH / GBK) issue((it + 2) % NSTAGE, (it + 2) * GBK);
        compute(it % NSTAGE);
    }

    // ---- fused attention scores (layers 1 & 2) ----
    if (asrc) {
#pragma unroll
        for (int mt = 0; mt < 2; mt++) {
#pragma unroll
            for (int i = 0; i < 2; i++) {
                float s = 0.f, d = 0.f;
#pragma unroll
                for (int nt = 0; nt < 8; nt++) {
                    int col = colBlk + wn * 64 + nt * 8 + tg * 2;
                    float s0 = asrc[col], s1 = asrc[col + 1];
                    float d0 = adst[col], d1 = adst[col + 1];
                    s += c[mt][nt][i * 2] * s0 + c[mt][nt][i * 2 + 1] * s1;
                    d += c[mt][nt][i * 2] * d0 + c[mt][nt][i * 2 + 1] * d1;
                }
                s += __shfl_xor_sync(0xffffffffu, s, 1);
                s += __shfl_xor_sync(0xffffffffu, s, 2);
                d += __shfl_xor_sync(0xffffffffu, d, 1);
                d += __shfl_xor_sync(0xffffffffu, d, 2);
                int row = rowBlk + wm * 32 + mt * 16 + gid + i * 8;
                if (tg == 0 && row < M) {
                    atomicAdd(&as_out[row], s);
                    atomicAdd(&ad_out[row], d);
                }
            }
        }
    }

    // ---- store C ----
#pragma unroll
    for (int mt = 0; mt < 2; mt++) {
#pragma unroll
        for (int i = 0; i < 2; i++) {
            int row = rowBlk + wm * 32 + mt * 16 + gid + i * 8;
            if (row >= M) continue;
#pragma unroll
            for (int nt = 0; nt < 8; nt++) {
                int col = colBlk + wn * 64 + nt * 8 + tg * 2;
                float v0 = c[mt][nt][i * 2 + 0];
                float v1 = c[mt][nt][i * 2 + 1];
                if (bias) { v0 += bias[col]; v1 += bias[col + 1]; }
                if (act) { v0 = fmaxf(v0, 0.f); v1 = fmaxf(v1, 0.f); }
                *(float2*)(C + (size_t)row * DH + col) = make_float2(v0, v1);
            }
        }
    }
}

// ---------------- fused softmax + aggregation (warp per node) ----------------
__global__ __launch_bounds__(256) void k_fusedagg(
    const float* __restrict__ h, const float* __restrict__ bias,
    float* __restrict__ out, const float* __restrict__ gas,
    const float* __restrict__ gad, int N)
{
    int node = blockIdx.x * 8 + (threadIdx.x >> 5);
    if (node >= N) return;
    int lane = threadIdx.x & 31;
    int beg = g_rowptr[node], end = g_rowptr[node + 1];
    float adn = gad[node];

    // online softmax stats, lane-strided over edges
    float m = -1e30f, ssum = 0.f;
    for (int p = beg + lane; p < end; p += 32) {
        int s = g_perm[p];
        float v = gas[s] + adn;
        v = (v > 0.f) ? v : 0.2f * v;
        float mn = fmaxf(m, v);
        ssum = ssum * __expf(m - mn) + __expf(v - mn);
        m = mn;
    }
#pragma unroll
    for (int o = 16; o; o >>= 1) {
        float mo = __shfl_xor_sync(0xffffffffu, m, o);
        float so = __shfl_xor_sync(0xffffffffu, ssum, o);
        float mn = fmaxf(m, mo);
        ssum = ssum * __expf(m - mn) + so * __expf(mo - mn);
        m = mn;
    }
    float inv = 1.0f / (ssum + 1e-16f);

    float4 acc0 = make_float4(0.f, 0.f, 0.f, 0.f), acc1 = acc0;
    for (int c0 = beg; c0 < end; c0 += 32) {
        int p = c0 + lane;
        float al = 0.f;
        int s = 0;
        if (p < end) {
            s = g_perm[p];
            float v = gas[s] + adn;
            v = (v > 0.f) ? v : 0.2f * v;
            al = __expf(v - m) * inv;
        }
        int cnt = min(32, end - c0);
        for (int j = 0; j < cnt; j++) {
            float a = __shfl_sync(0xffffffffu, al, j);
            int ss = __shfl_sync(0xffffffffu, s, j);
            const float4* hr = (const float4*)(h + (size_t)ss * DH);
            float4 v0 = hr[lane], v1 = hr[lane + 32];
            acc0.x += a * v0.x; acc0.y += a * v0.y;
            acc0.z += a * v0.z; acc0.w += a * v0.w;
            acc1.x += a * v1.x; acc1.y += a * v1.y;
            acc1.z += a * v1.z; acc1.w += a * v1.w;
        }
    }
    float4 b0 = ((const float4*)bias)[lane];
    float4 b1 = ((const float4*)bias)[lane + 32];
    float4 o0, o1;
    o0.x = rnd_tf32(fmaxf(acc0.x + b0.x, 0.f)); o0.y = rnd_tf32(fmaxf(acc0.y + b0.y, 0.f));
    o0.z = rnd_tf32(fmaxf(acc0.z + b0.z, 0.f)); o0.w = rnd_tf32(fmaxf(acc0.w + b0.w, 0.f));
    o1.x = rnd_tf32(fmaxf(acc1.x + b1.x, 0.f)); o1.y = rnd_tf32(fmaxf(acc1.y + b1.y, 0.f));
    o1.z = rnd_tf32(fmaxf(acc1.z + b1.z, 0.f)); o1.w = rnd_tf32(fmaxf(acc1.w + b1.w, 0.f));
    float4* orow = (float4*)(out + (size_t)node * DH);
    orow[lane] = o0;
    orow[lane + 32] = o1;
}

// ---------------- final head: out = tanh(x @ Wm2 + bm2), 256 -> 8 ----------------
__global__ __launch_bounds__(256) void k_mlp2(
    const float* __restrict__ x, const float* __restrict__ W,
    const float* __restrict__ b, float* __restrict__ out, int N)
{
    __shared__ float wT[8][256];
    for (int i = threadIdx.x; i < 2048; i += 256) {
        int k = i >> 3, o = i & 7;
        wT[o][k] = W[i];
    }
    __syncthreads();
    int node = blockIdx.x * 8 + (threadIdx.x >> 5);
    if (node >= N) return;
    int lane = threadIdx.x & 31;
    const float* row = x + (size_t)node * DH;
    float p[8] = {0, 0, 0, 0, 0, 0, 0, 0};
#pragma unroll
    for (int j = 0; j < 8; j++) {
        int k = lane + 32 * j;
        float xv = row[k];
#pragma unroll
        for (int o = 0; o < 8; o++) p[o] += xv * wT[o][k];
    }
#pragma unroll
    for (int o = 0; o < 8; o++)
#pragma unroll
        for (int off = 16; off; off >>= 1)
            p[o] += __shfl_xor_sync(0xffffffffu, p[o], off);
    if (lane < 8) {
        float v = p[0];
#pragma unroll
        for (int o = 1; o < 8; o++) if (lane == o) v = p[o];
        out[(size_t)node * AOUT + lane] = tanhf(v + b[lane]);
    }
}

// ---------------- launch ----------------
extern "C" void kernel_launch(void* const* d_in, const int* in_sizes, int n_in,
                              void* d_out, int out_size)
{
    const float* obs = (const float*)d_in[0];
    const int*   ei  = (const int*)d_in[1];
    const float* W1  = (const float*)d_in[2];
    const float* a1s = (const float*)d_in[3];
    const float* a1d = (const float*)d_in[4];
    const float* b1  = (const float*)d_in[5];
    const float* W2  = (const float*)d_in[6];
    const float* a2s = (const float*)d_in[7];
    const float* a2d = (const float*)d_in[8];
    const float* b2  = (const float*)d_in[9];
    const float* Wm1 = (const float*)d_in[10];
    const float* bm1 = (const float*)d_in[11];
    const float* Wm2 = (const float*)d_in[12];
    const float* bm2 = (const float*)d_in[13];
    float* out = (float*)d_out;

    const int N  = in_sizes[0] / DH;
    const int E  = in_sizes[1] / 2;

    float *bufA, *bufB, *obsr, *w1r, *w2r, *wm1r;
    float *as1, *ad1, *as2, *ad2;
    cudaGetSymbolAddress((void**)&bufA, g_bufA);
    cudaGetSymbolAddress((void**)&bufB, g_bufB);
    cudaGetSymbolAddress((void**)&obsr, g_obsr);
    cudaGetSymbolAddress((void**)&w1r,  g_w1r);
    cudaGetSymbolAddress((void**)&w2r,  g_w2r);
    cudaGetSymbolAddress((void**)&wm1r, g_wm1r);
    cudaGetSymbolAddress((void**)&as1,  g_as1);
    cudaGetSymbolAddress((void**)&ad1,  g_ad1);
    cudaGetSymbolAddress((void**)&as2,  g_as2);
    cudaGetSymbolAddress((void**)&ad2,  g_ad2);

    cudaFuncSetAttribute(k_gemm_tf32, cudaFuncAttributeMaxDynamicSharedMemorySize, SMEM_GEMM);

    const int T = 256;
    dim3 gemmGrid(DH / GBN, (N + GBM - 1) / GBM);
    int nodeBlocks = (N + 7) / 8;
    int edgeBlocks = (E + T - 1) / T;
    int prepTotal  = N * DH + 3 * 65536 + N;

    // 1: prep (tf32 rounding, zero cursors + score accumulators)
    k_prep<<<(prepTotal + T - 1) / T, T>>>(obs, W1, W2, Wm1, N);
    // 2-3: CSR count (real edges only, int4) + scan (adds self-loops)
    k_count<<<(E / 4 + T - 1) / T, T>>>(ei, E);
    k_scan<<<1, 1024>>>(N);
    // 4: GAT layer-1 GEMM + fused scores  (this launch gets ncu-profiled)
    k_gemm_tf32<<<gemmGrid, 256, SMEM_GEMM>>>(obsr, w1r, bufA, N, nullptr, 0,
                                              a1s, a1d, as1, ad1);
    // 5: CSR scatter (real edges only)
    k_scatter<<<edgeBlocks, T>>>(ei, E);
    // 6: layer-1 softmax+aggregate (relu + b1, tf32-round for next GEMM)
    k_fusedagg<<<nodeBlocks, T>>>(bufA, b1, bufB, as1, ad1, N);
    // 7-8: GAT layer 2
    k_gemm_tf32<<<gemmGrid, 256, SMEM_GEMM>>>(bufB, w2r, bufA, N, nullptr, 0,
                                              a2s, a2d, as2, ad2);
    k_fusedagg<<<nodeBlocks, T>>>(bufA, b2, bufB, as2, ad2, N);
    // 9: MLP layer 1 (relu + bm1)
    k_gemm_tf32<<<gemmGrid, 256, SMEM_GEMM>>>(bufB, wm1r, bufA, N, bm1, 1,
                                              nullptr, nullptr, nullptr, nullptr);
    // 10: final head
    k_mlp2<<<nodeBlocks, T>>>(bufA, Wm2, bm2, out, N);
}

// round 5
// speedup vs baseline: 1.0956x; 1.0956x over previous
#include <cuda_runtime.h>
#include <cuda_fp16.h>
#include <math.h>

#define DH 256          // feature dim (D == H == 256)
#define AOUT 8
#define MAXN 20000
#define MAXE 320000
#define MAXT (MAXN + MAXE)

// ---------------- device scratch (no allocations allowed) ----------------
__device__ float    g_bufA[(size_t)MAXN * DH];   // also reused as __half
__device__ float    g_bufB[(size_t)MAXN * DH];
__device__ float    g_obsr[(size_t)MAXN * DH];   // tf32-rounded obs
__device__ float    g_w1r[DH * DH];
__device__ float    g_w2r[DH * DH];
__device__ float    g_wm1r[DH * DH];
__device__ float    g_as1[MAXN];
__device__ float    g_ad1[MAXN];
__device__ float    g_as2[MAXN];
__device__ float    g_ad2[MAXN];
__device__ int      g_rowptr[MAXN + 1];
__device__ int      g_cursor[MAXN];
__device__ int      g_perm[MAXT];       // src node ids grouped by dst

__device__ __forceinline__ float rnd_tf32(float x) {
    unsigned u;
    asm("cvt.rna.tf32.f32 %0, %1;" : "=r"(u) : "f"(x));
    return __uint_as_float(u);
}

// ---------------- prep: round inputs to tf32, zero cursors + score accs ----------------
__global__ void k_prep(const float* __restrict__ obs,
                       const float* __restrict__ W1,
                       const float* __restrict__ W2,
                       const float* __restrict__ Wm1, int N)
{
    int nobs = N * DH;
    int i = blockIdx.x * blockDim.x + threadIdx.x;
    if (i < nobs) {
        g_obsr[i] = rnd_tf32(obs[i]);
    } else if (i < nobs + 65536) {
        int j = i - nobs;
        g_w1r[j] = rnd_tf32(W1[j]);
    } else if (i < nobs + 2 * 65536) {
        int j = i - nobs - 65536;
        g_w2r[j] = rnd_tf32(W2[j]);
    } else if (i < nobs + 3 * 65536) {
        int j = i - nobs - 2 * 65536;
        g_wm1r[j] = rnd_tf32(Wm1[j]);
    } else {
        int j = i - nobs - 3 * 65536;
        if (j < N) {
            g_cursor[j] = 0;
            g_as1[j] = 0.f; g_ad1[j] = 0.f;
            g_as2[j] = 0.f; g_ad2[j] = 0.f;
        }
    }
}

// ---------------- CSR build (self-loops handled implicitly) ----------------
__global__ void k_count(const int* __restrict__ ei, int E) {
    int q = blockIdx.x * blockDim.x + threadIdx.x;
    if (q * 4 >= E) return;
    int4 d4 = *(const int4*)(ei + E + q * 4);
    atomicAdd(&g_cursor[d4.x], 1);
    atomicAdd(&g_cursor[d4.y], 1);
    atomicAdd(&g_cursor[d4.z], 1);
    atomicAdd(&g_cursor[d4.w], 1);
}

__global__ void k_scan(int N) {
    __shared__ int sh[1024];
    int tid = threadIdx.x;
    int per = (N + 1023) >> 10;
    int b0 = tid * per;
    int b1 = min(b0 + per, N);
    int loc = 0;
    for (int i = b0; i < b1; i++) loc += g_cursor[i] + 1;   // +1 self-loop
    sh[tid] = loc;
    __syncthreads();
#pragma unroll
    for (int o = 1; o < 1024; o <<= 1) {
        int t = (tid >= o) ? sh[tid - o] : 0;
        __syncthreads();
        sh[tid] += t;
        __syncthreads();
    }
    int run = (tid == 0) ? 0 : sh[tid - 1];
    for (int i = b0; i < b1; i++) {
        int c = g_cursor[i] + 1;
        g_rowptr[i] = run;
        g_perm[run] = i;            // self-loop at group head, no atomic
        g_cursor[i] = run + 1;
        run += c;
    }
    if (tid == 1023) g_rowptr[N] = sh[1023];
}

__global__ void k_scatter(const int* __restrict__ ei, int E) {
    int e = blockIdx.x * blockDim.x + threadIdx.x;
    if (e >= E) return;
    int s = ei[e], d = ei[E + e];
    int pos = atomicAdd(&g_cursor[d], 1);
    g_perm[pos] = s;
}

// ---------------- tf32 tensor-core GEMM: C[M,256] = A[M,256] @ B[256,256] ----------------
// CTA 64x128, BK=16, 4 warps (each 32x64), 3-stage cp.async, 4 CTAs/SM.
#define GBM 64
#define GBN 128
#define GBK 16
#define ASTR 20     // 16 + 4 pad (conflict-free mod 32)
#define BSTR 136    // 128 + 8 pad (conflict-free mod 32)
#define ASZ (GBM * ASTR)     // 1280
#define BSZ (GBK * BSTR)     // 2176
#define NSTAGE 3
#define SMEM_GEMM ((NSTAGE * (ASZ + BSZ)) * 4)   // 41472 bytes

__global__ __launch_bounds__(128, 4) void k_gemm_tf32(
    const float* __restrict__ A, const float* __restrict__ B,
    float* __restrict__ C, __half* __restrict__ Ch, int M,
    const float* __restrict__ bias, int act,
    const float* __restrict__ asrc, const float* __restrict__ adst,
    float* as_out, float* ad_out)
{
    extern __shared__ float sm[];
    float* As = sm;                    // [NSTAGE][GBM][ASTR]
    float* Bs = sm + NSTAGE * ASZ;     // [NSTAGE][GBK][BSTR]

    const int tid = threadIdx.x;
    const int warpId = tid >> 5, lane = tid & 31;
    const int gid = lane >> 2, tg = lane & 3;
    const int wm = warpId >> 1, wn = warpId & 1;    // 2x2 warp grid
    const int rowBlk = blockIdx.y * GBM;
    const int colBlk = blockIdx.x * GBN;

    float c[2][8][4];
#pragma unroll
    for (int mt = 0; mt < 2; mt++)
#pragma unroll
        for (int nt = 0; nt < 8; nt++)
#pragma unroll
            for (int q = 0; q < 4; q++) c[mt][nt][q] = 0.f;

    auto issue = [&](int buf, int k0) {
#pragma unroll
        for (int i = 0; i < 2; i++) {           // A: 64x16 = 256 float4
            int f = tid + i * 128;
            int r = f >> 2, kq = (f & 3) << 2;
            int grow = rowBlk + r;
            const float* src = A + (size_t)grow * DH + k0 + kq;
            unsigned dst = (unsigned)__cvta_generic_to_shared(&As[buf * ASZ + r * ASTR + kq]);
            int sz = (grow < M) ? 16 : 0;
            asm volatile("cp.async.cg.shared.global [%0], [%1], 16, %2;\n"
                         :: "r"(dst), "l"(src), "r"(sz));
        }
#pragma unroll
        for (int i = 0; i < 4; i++) {           // B: 16x128 = 512 float4
            int f = tid + i * 128;
            int kr = f >> 5, nq = (f & 31) << 2;
            const float* src = B + (size_t)(k0 + kr) * DH + colBlk + nq;
            unsigned dst = (unsigned)__cvta_generic_to_shared(&Bs[buf * BSZ + kr * BSTR + nq]);
            asm volatile("cp.async.cg.shared.global [%0], [%1], 16;\n"
                         :: "r"(dst), "l"(src));
        }
        asm volatile("cp.async.commit_group;\n");
    };

    auto compute = [&](int buf) {
#pragma unroll
        for (int ks = 0; ks < 2; ks++) {
            const int kk = ks * 8;
            float a[2][4], b[8][2];
#pragma unroll
            for (int mt = 0; mt < 2; mt++) {
                const float* ab = &As[buf * ASZ + (wm * 32 + mt * 16 + gid) * ASTR + kk + tg];
                a[mt][0] = ab[0];
                a[mt][1] = ab[8 * ASTR];
                a[mt][2] = ab[4];
                a[mt][3] = ab[8 * ASTR + 4];
            }
#pragma unroll
            for (int nt = 0; nt < 8; nt++) {
                const float* bb = &Bs[buf * BSZ + (kk + tg) * BSTR + wn * 64 + nt * 8 + gid];
                b[nt][0] = bb[0];
                b[nt][1] = bb[4 * BSTR];
            }
#pragma unroll
            for (int mt = 0; mt < 2; mt++)
#pragma unroll
                for (int nt = 0; nt < 8; nt++) {
                    asm volatile(
                        "mma.sync.aligned.m16n8k8.row.col.f32.tf32.tf32.f32 "
                        "{%0,%1,%2,%3}, {%4,%5,%6,%7}, {%8,%9}, {%0,%1,%2,%3};\n"
                        : "+f"(c[mt][nt][0]), "+f"(c[mt][nt][1]),
                          "+f"(c[mt][nt][2]), "+f"(c[mt][nt][3])
                        : "r"(__float_as_uint(a[mt][0])), "r"(__float_as_uint(a[mt][1])),
                          "r"(__float_as_uint(a[mt][2])), "r"(__float_as_uint(a[mt][3])),
                          "r"(__float_as_uint(b[nt][0])), "r"(__float_as_uint(b[nt][1])));
                }
        }
    };

    issue(0, 0);
    issue(1, GBK);
#pragma unroll
    for (int it = 0; it < DH / GBK; it++) {
        if (it < DH / GBK - 1)
            asm volatile("cp.async.wait_group 1;\n");
        else
            asm volatile("cp.async.wait_group 0;\n");
        __syncthreads();
        if (it + 2 < DH / GBK) issue((it + 2) % NSTAGE, (it + 2) * GBK);
        compute(it % NSTAGE);
    }

    // ---- fused attention scores (layers 1 & 2; fp32 accumulators) ----
    if (asrc) {
#pragma unroll
        for (int mt = 0; mt < 2; mt++) {
#pragma unroll
            for (int i = 0; i < 2; i++) {
                float s = 0.f, d = 0.f;
#pragma unroll
                for (int nt = 0; nt < 8; nt++) {
                    int col = colBlk + wn * 64 + nt * 8 + tg * 2;
                    s += c[mt][nt][i * 2] * asrc[col] + c[mt][nt][i * 2 + 1] * asrc[col + 1];
                    d += c[mt][nt][i * 2] * adst[col] + c[mt][nt][i * 2 + 1] * adst[col + 1];
                }
                s += __shfl_xor_sync(0xffffffffu, s, 1);
                s += __shfl_xor_sync(0xffffffffu, s, 2);
                d += __shfl_xor_sync(0xffffffffu, d, 1);
                d += __shfl_xor_sync(0xffffffffu, d, 2);
                int row = rowBlk + wm * 32 + mt * 16 + gid + i * 8;
                if (tg == 0 && row < M) {
                    atomicAdd(&as_out[row], s);
                    atomicAdd(&ad_out[row], d);
                }
            }
        }
    }

    // ---- store C (fp16 for aggregation path, fp32 otherwise) ----
#pragma unroll
    for (int mt = 0; mt < 2; mt++) {
#pragma unroll
        for (int i = 0; i < 2; i++) {
            int row = rowBlk + wm * 32 + mt * 16 + gid + i * 8;
            if (row >= M) continue;
#pragma unroll
            for (int nt = 0; nt < 8; nt++) {
                int col = colBlk + wn * 64 + nt * 8 + tg * 2;
                float v0 = c[mt][nt][i * 2 + 0];
                float v1 = c[mt][nt][i * 2 + 1];
                if (bias) { v0 += bias[col]; v1 += bias[col + 1]; }
                if (act) { v0 = fmaxf(v0, 0.f); v1 = fmaxf(v1, 0.f); }
                if (Ch) {
                    *(__half2*)(Ch + (size_t)row * DH + col) =
                        __floats2half2_rn(v0, v1);
                } else {
                    *(float2*)(C + (size_t)row * DH + col) = make_float2(v0, v1);
                }
            }
        }
    }
}

// ---------------- fused softmax + aggregation (warp per node, fp16 gather) ----------------
__global__ __launch_bounds__(256) void k_fusedagg(
    const __half* __restrict__ h, const float* __restrict__ bias,
    float* __restrict__ out, const float* __restrict__ gas,
    const float* __restrict__ gad, int N)
{
    int node = blockIdx.x * 8 + (threadIdx.x >> 5);
    if (node >= N) return;
    int lane = threadIdx.x & 31;
    int beg = g_rowptr[node], end = g_rowptr[node + 1];
    float adn = gad[node];

    // online softmax stats, lane-strided over edges
    float m = -1e30f, ssum = 0.f;
    for (int p = beg + lane; p < end; p += 32) {
        int s = g_perm[p];
        float v = gas[s] + adn;
        v = (v > 0.f) ? v : 0.2f * v;
        float mn = fmaxf(m, v);
        ssum = ssum * __expf(m - mn) + __expf(v - mn);
        m = mn;
    }
#pragma unroll
    for (int o = 16; o; o >>= 1) {
        float mo = __shfl_xor_sync(0xffffffffu, m, o);
        float so = __shfl_xor_sync(0xffffffffu, ssum, o);
        float mn = fmaxf(m, mo);
        ssum = ssum * __expf(m - mn) + so * __expf(mo - mn);
        m = mn;
    }
    float inv = 1.0f / (ssum + 1e-16f);

    // aggregate: lane owns 8 contiguous columns [lane*8, lane*8+8)
    float acc[8];
#pragma unroll
    for (int q = 0; q < 8; q++) acc[q] = 0.f;

    for (int c0 = beg; c0 < end; c0 += 32) {
        int p = c0 + lane;
        float al = 0.f;
        int s = 0;
        if (p < end) {
            s = g_perm[p];
            float v = gas[s] + adn;
            v = (v > 0.f) ? v : 0.2f * v;
            al = __expf(v - m) * inv;
        }
        int cnt = min(32, end - c0);
        for (int j = 0; j < cnt; j++) {
            float a = __shfl_sync(0xffffffffu, al, j);
            int ss = __shfl_sync(0xffffffffu, s, j);
            uint4 v = ((const uint4*)(h + (size_t)ss * DH))[lane];
            const __half2* hp = (const __half2*)&v;
            float2 f0 = __half22float2(hp[0]);
            float2 f1 = __half22float2(hp[1]);
            float2 f2 = __half22float2(hp[2]);
            float2 f3 = __half22float2(hp[3]);
            acc[0] += a * f0.x; acc[1] += a * f0.y;
            acc[2] += a * f1.x; acc[3] += a * f1.y;
            acc[4] += a * f2.x; acc[5] += a * f2.y;
            acc[6] += a * f3.x; acc[7] += a * f3.y;
        }
    }

    float4 b0 = ((const float4*)bias)[lane * 2];
    float4 b1 = ((const float4*)bias)[lane * 2 + 1];
    float4 o0, o1;
    o0.x = rnd_tf32(fmaxf(acc[0] + b0.x, 0.f)); o0.y = rnd_tf32(fmaxf(acc[1] + b0.y, 0.f));
    o0.z = rnd_tf32(fmaxf(acc[2] + b0.z, 0.f)); o0.w = rnd_tf32(fmaxf(acc[3] + b0.w, 0.f));
    o1.x = rnd_tf32(fmaxf(acc[4] + b1.x, 0.f)); o1.y = rnd_tf32(fmaxf(acc[5] + b1.y, 0.f));
    o1.z = rnd_tf32(fmaxf(acc[6] + b1.z, 0.f)); o1.w = rnd_tf32(fmaxf(acc[7] + b1.w, 0.f));
    float4* orow = (float4*)(out + (size_t)node * DH + lane * 8);
    orow[0] = o0;
    orow[1] = o1;
}

// ---------------- final head: out = tanh(x @ Wm2 + bm2), 256 -> 8 ----------------
__global__ __launch_bounds__(256) void k_mlp2(
    const float* __restrict__ x, const float* __restrict__ W,
    const float* __restrict__ b, float* __restrict__ out, int N)
{
    __shared__ float wT[8][256];
    for (int i = threadIdx.x; i < 2048; i += 256) {
        int k = i >> 3, o = i & 7;
        wT[o][k] = W[i];
    }
    __syncthreads();
    int node = blockIdx.x * 8 + (threadIdx.x >> 5);
    if (node >= N) return;
    int lane = threadIdx.x & 31;
    const float* row = x + (size_t)node * DH;
    float p[8] = {0, 0, 0, 0, 0, 0, 0, 0};
#pragma unroll
    for (int j = 0; j < 8; j++) {
        int k = lane + 32 * j;
        float xv = row[k];
#pragma unroll
        for (int o = 0; o < 8; o++) p[o] += xv * wT[o][k];
    }
#pragma unroll
    for (int o = 0; o < 8; o++)
#pragma unroll
        for (int off = 16; off; off >>= 1)
            p[o] += __shfl_xor_sync(0xffffffffu, p[o], off);
    if (lane < 8) {
        float v = p[0];
#pragma unroll
        for (int o = 1; o < 8; o++) if (lane == o) v = p[o];
        out[(size_t)node * AOUT + lane] = tanhf(v + b[lane]);
    }
}

// ---------------- launch ----------------
extern "C" void kernel_launch(void* const* d_in, const int* in_sizes, int n_in,
                              void* d_out, int out_size)
{
    const float* obs = (const float*)d_in[0];
    const int*   ei  = (const int*)d_in[1];
    const float* W1  = (const float*)d_in[2];
    const float* a1s = (const float*)d_in[3];
    const float* a1d = (const float*)d_in[4];
    const float* b1  = (const float*)d_in[5];
    const float* W2  = (const float*)d_in[6];
    const float* a2s = (const float*)d_in[7];
    const float* a2d = (const float*)d_in[8];
    const float* b2  = (const float*)d_in[9];
    const float* Wm1 = (const float*)d_in[10];
    const float* bm1 = (const float*)d_in[11];
    const float* Wm2 = (const float*)d_in[12];
    const float* bm2 = (const float*)d_in[13];
    float* out = (float*)d_out;

    const int N  = in_sizes[0] / DH;
    const int E  = in_sizes[1] / 2;

    float *bufA, *bufB, *obsr, *w1r, *w2r, *wm1r;
    float *as1, *ad1, *as2, *ad2;
    cudaGetSymbolAddress((void**)&bufA, g_bufA);
    cudaGetSymbolAddress((void**)&bufB, g_bufB);
    cudaGetSymbolAddress((void**)&obsr, g_obsr);
    cudaGetSymbolAddress((void**)&w1r,  g_w1r);
    cudaGetSymbolAddress((void**)&w2r,  g_w2r);
    cudaGetSymbolAddress((void**)&wm1r, g_wm1r);
    cudaGetSymbolAddress((void**)&as1,  g_as1);
    cudaGetSymbolAddress((void**)&ad1,  g_ad1);
    cudaGetSymbolAddress((void**)&as2,  g_as2);
    cudaGetSymbolAddress((void**)&ad2,  g_ad2);
    __half* bufAh = (__half*)bufA;     // fp16 view for the gather path

    cudaFuncSetAttribute(k_gemm_tf32, cudaFuncAttributeMaxDynamicSharedMemorySize, SMEM_GEMM);

    const int T = 256;
    dim3 gemmGrid(DH / GBN, (N + GBM - 1) / GBM);   // (2, 313)
    int nodeBlocks = (N + 7) / 8;
    int edgeBlocks = (E + T - 1) / T;
    int prepTotal  = N * DH + 3 * 65536 + N;

    // 1: prep (tf32 rounding, zero cursors + score accumulators)
    k_prep<<<(prepTotal + T - 1) / T, T>>>(obs, W1, W2, Wm1, N);
    // 2-3: CSR count (real edges only, int4) + scan (adds self-loops)
    k_count<<<(E / 4 + T - 1) / T, T>>>(ei, E);
    k_scan<<<1, 1024>>>(N);
    // 4: GAT layer-1 GEMM (fp16 h out) + fused scores  (ncu-profiled launch)
    k_gemm_tf32<<<gemmGrid, 128, SMEM_GEMM>>>(obsr, w1r, nullptr, bufAh, N,
                                              nullptr, 0, a1s, a1d, as1, ad1);
    // 5: CSR scatter (real edges only)
    k_scatter<<<edgeBlocks, T>>>(ei, E);
    // 6: layer-1 softmax+aggregate (relu + b1, tf32-round for next GEMM)
    k_fusedagg<<<nodeBlocks, T>>>(bufAh, b1, bufB, as1, ad1, N);
    // 7-8: GAT layer 2
    k_gemm_tf32<<<gemmGrid, 128, SMEM_GEMM>>>(bufB, w2r, nullptr, bufAh, N,
                                              nullptr, 0, a2s, a2d, as2, ad2);
    k_fusedagg<<<nodeBlocks, T>>>(bufAh, b2, bufB, as2, ad2, N);
    // 9: MLP layer 1 (relu + bm1, fp32 out for the head)
    float* bufC = obsr;   // obs no longer needed; reuse as fp32 scratch
    k_gemm_tf32<<<gemmGrid, 128, SMEM_GEMM>>>(bufB, wm1r, bufC, nullptr, N,
                                              bm1, 1, nullptr, nullptr, nullptr, nullptr);
    // 10: final head
    k_mlp2<<<nodeBlocks, T>>>(bufC, Wm2, bm2, out, N);
}

// round 6
// speedup vs baseline: 1.1441x; 1.0442x over previous
#include <cuda_runtime.h>
#include <cuda_fp16.h>
#include <math.h>

#define DH 256          // feature dim (D == H == 256)
#define AOUT 8
#define MAXN 20000
#define MAXE 320000
#define MAXT (MAXN + MAXE)

// ---------------- device scratch (no allocations allowed) ----------------
__device__ float    g_bufA[(size_t)MAXN * DH];   // fp16 view for gather path
__device__ float    g_bufB[(size_t)MAXN * DH];
__device__ float    g_bufC[(size_t)MAXN * DH];   // fp32 scratch (mlp1 out)
__device__ float    g_w1r[DH * DH];
__device__ float    g_w2r[DH * DH];
__device__ float    g_wm1r[DH * DH];
__device__ float    g_as1[MAXN];
__device__ float    g_ad1[MAXN];
__device__ float    g_as2[MAXN];
__device__ float    g_ad2[MAXN];
__device__ int      g_rowptr[MAXN + 1];
__device__ int      g_cursor[MAXN];
__device__ int      g_perm[MAXT];       // src node ids grouped by dst

__device__ __forceinline__ float rnd_tf32(float x) {
    unsigned u;
    asm("cvt.rna.tf32.f32 %0, %1;" : "=r"(u) : "f"(x));
    return __uint_as_float(u);
}

// ---------------- prep: round weights to tf32, zero cursors + score accs ----------------
__global__ void k_prep(const float* __restrict__ W1,
                       const float* __restrict__ W2,
                       const float* __restrict__ Wm1, int N)
{
    int i = blockIdx.x * blockDim.x + threadIdx.x;
    if (i < 65536) {
        g_w1r[i] = rnd_tf32(W1[i]);
    } else if (i < 2 * 65536) {
        int j = i - 65536;
        g_w2r[j] = rnd_tf32(W2[j]);
    } else if (i < 3 * 65536) {
        int j = i - 2 * 65536;
        g_wm1r[j] = rnd_tf32(Wm1[j]);
    } else {
        int j = i - 3 * 65536;
        if (j < N) {
            g_cursor[j] = 0;
            g_as1[j] = 0.f; g_ad1[j] = 0.f;
            g_as2[j] = 0.f; g_ad2[j] = 0.f;
        }
    }
}

// ---------------- CSR build (self-loops handled implicitly) ----------------
__global__ void k_count(const int* __restrict__ ei, int E) {
    int q = blockIdx.x * blockDim.x + threadIdx.x;
    if (q * 4 >= E) return;
    int4 d4 = *(const int4*)(ei + E + q * 4);
    atomicAdd(&g_cursor[d4.x], 1);
    atomicAdd(&g_cursor[d4.y], 1);
    atomicAdd(&g_cursor[d4.z], 1);
    atomicAdd(&g_cursor[d4.w], 1);
}

__global__ void k_scan(int N) {
    __shared__ int sh[1024];
    int tid = threadIdx.x;
    int per = (N + 1023) >> 10;
    int b0 = tid * per;
    int b1 = min(b0 + per, N);
    int loc = 0;
    for (int i = b0; i < b1; i++) loc += g_cursor[i] + 1;   // +1 self-loop
    sh[tid] = loc;
    __syncthreads();
#pragma unroll
    for (int o = 1; o < 1024; o <<= 1) {
        int t = (tid >= o) ? sh[tid - o] : 0;
        __syncthreads();
        sh[tid] += t;
        __syncthreads();
    }
    int run = (tid == 0) ? 0 : sh[tid - 1];
    for (int i = b0; i < b1; i++) {
        int c = g_cursor[i] + 1;
        g_rowptr[i] = run;
        g_perm[run] = i;            // self-loop at group head, no atomic
        g_cursor[i] = run + 1;
        run += c;
    }
    if (tid == 1023) g_rowptr[N] = sh[1023];
}

__global__ void k_scatter(const int* __restrict__ ei, int E) {
    int e = blockIdx.x * blockDim.x + threadIdx.x;
    if (e >= E) return;
    int s = ei[e], d = ei[E + e];
    int pos = atomicAdd(&g_cursor[d], 1);
    g_perm[pos] = s;
}

// ---------------- tf32 tensor-core GEMM: C[M,256] = A[M,256] @ B[256,256] ----------------
// CTA 64x128, BK=16, 4 warps (each 32x64), 3-stage cp.async, 4 CTAs/SM.
// Fragment loads hoisted ahead of MMAs to batch LDS latency.
#define GBM 64
#define GBN 128
#define GBK 16
#define ASTR 20     // 16 + 4 pad (conflict-free mod 32)
#define BSTR 136    // 128 + 8 pad (conflict-free mod 32)
#define ASZ (GBM * ASTR)     // 1280
#define BSZ (GBK * BSTR)     // 2176
#define NSTAGE 3
#define SMEM_GEMM ((NSTAGE * (ASZ + BSZ)) * 4)   // 41472 bytes

__global__ __launch_bounds__(128, 4) void k_gemm_tf32(
    const float* __restrict__ A, const float* __restrict__ B,
    float* __restrict__ C, __half* __restrict__ Ch, int M,
    const float* __restrict__ bias, int act, int roundA,
    const float* __restrict__ asrc, const float* __restrict__ adst,
    float* as_out, float* ad_out)
{
    extern __shared__ float sm[];
    float* As = sm;                    // [NSTAGE][GBM][ASTR]
    float* Bs = sm + NSTAGE * ASZ;     // [NSTAGE][GBK][BSTR]

    const int tid = threadIdx.x;
    const int warpId = tid >> 5, lane = tid & 31;
    const int gid = lane >> 2, tg = lane & 3;
    const int wm = warpId >> 1, wn = warpId & 1;    // 2x2 warp grid
    const int rowBlk = blockIdx.y * GBM;
    const int colBlk = blockIdx.x * GBN;

    float c[2][8][4];
#pragma unroll
    for (int mt = 0; mt < 2; mt++)
#pragma unroll
        for (int nt = 0; nt < 8; nt++)
#pragma unroll
            for (int q = 0; q < 4; q++) c[mt][nt][q] = 0.f;

    auto issue = [&](int buf, int k0) {
#pragma unroll
        for (int i = 0; i < 2; i++) {           // A: 64x16 = 256 float4
            int f = tid + i * 128;
            int r = f >> 2, kq = (f & 3) << 2;
            int grow = rowBlk + r;
            const float* src = A + (size_t)grow * DH + k0 + kq;
            unsigned dst = (unsigned)__cvta_generic_to_shared(&As[buf * ASZ + r * ASTR + kq]);
            int sz = (grow < M) ? 16 : 0;
            asm volatile("cp.async.cg.shared.global [%0], [%1], 16, %2;\n"
                         :: "r"(dst), "l"(src), "r"(sz));
        }
#pragma unroll
        for (int i = 0; i < 4; i++) {           // B: 16x128 = 512 float4
            int f = tid + i * 128;
            int kr = f >> 5, nq = (f & 31) << 2;
            const float* src = B + (size_t)(k0 + kr) * DH + colBlk + nq;
            unsigned dst = (unsigned)__cvta_generic_to_shared(&Bs[buf * BSZ + kr * BSTR + nq]);
            asm volatile("cp.async.cg.shared.global [%0], [%1], 16;\n"
                         :: "r"(dst), "l"(src));
        }
        asm volatile("cp.async.commit_group;\n");
    };

    auto compute = [&](int buf) {
        // hoist ALL A fragments (both k-slices) — 16 independent LDS
        float a[2][2][4];
#pragma unroll
        for (int ks = 0; ks < 2; ks++) {
            const int kk = ks * 8;
#pragma unroll
            for (int mt = 0; mt < 2; mt++) {
                const float* ab = &As[buf * ASZ + (wm * 32 + mt * 16 + gid) * ASTR + kk + tg];
                a[ks][mt][0] = ab[0];
                a[ks][mt][1] = ab[8 * ASTR];
                a[ks][mt][2] = ab[4];
                a[ks][mt][3] = ab[8 * ASTR + 4];
            }
        }
        if (roundA) {
#pragma unroll
            for (int ks = 0; ks < 2; ks++)
#pragma unroll
                for (int mt = 0; mt < 2; mt++)
#pragma unroll
                    for (int q = 0; q < 4; q++)
                        a[ks][mt][q] = rnd_tf32(a[ks][mt][q]);
        }
        float b[8][2];
        // B fragments for ks=0 — 16 more independent LDS
#pragma unroll
        for (int nt = 0; nt < 8; nt++) {
            const float* bb = &Bs[buf * BSZ + tg * BSTR + wn * 64 + nt * 8 + gid];
            b[nt][0] = bb[0];
            b[nt][1] = bb[4 * BSTR];
        }
        // MMA ks=0 (overlaps nothing behind it — loads already in flight)
#pragma unroll
        for (int mt = 0; mt < 2; mt++)
#pragma unroll
            for (int nt = 0; nt < 8; nt++)
                asm volatile(
                    "mma.sync.aligned.m16n8k8.row.col.f32.tf32.tf32.f32 "
                    "{%0,%1,%2,%3}, {%4,%5,%6,%7}, {%8,%9}, {%0,%1,%2,%3};\n"
                    : "+f"(c[mt][nt][0]), "+f"(c[mt][nt][1]),
                      "+f"(c[mt][nt][2]), "+f"(c[mt][nt][3])
                    : "r"(__float_as_uint(a[0][mt][0])), "r"(__float_as_uint(a[0][mt][1])),
                      "r"(__float_as_uint(a[0][mt][2])), "r"(__float_as_uint(a[0][mt][3])),
                      "r"(__float_as_uint(b[nt][0])), "r"(__float_as_uint(b[nt][1])));
        // B fragments ks=1, then MMA ks=1
#pragma unroll
        for (int nt = 0; nt < 8; nt++) {
            const float* bb = &Bs[buf * BSZ + (8 + tg) * BSTR + wn * 64 + nt * 8 + gid];
            b[nt][0] = bb[0];
            b[nt][1] = bb[4 * BSTR];
        }
#pragma unroll
        for (int mt = 0; mt < 2; mt++)
#pragma unroll
            for (int nt = 0; nt < 8; nt++)
                asm volatile(
                    "mma.sync.aligned.m16n8k8.row.col.f32.tf32.tf32.f32 "
                    "{%0,%1,%2,%3}, {%4,%5,%6,%7}, {%8,%9}, {%0,%1,%2,%3};\n"
                    : "+f"(c[mt][nt][0]), "+f"(c[mt][nt][1]),
                      "+f"(c[mt][nt][2]), "+f"(c[mt][nt][3])
                    : "r"(__float_as_uint(a[1][mt][0])), "r"(__float_as_uint(a[1][mt][1])),
                      "r"(__float_as_uint(a[1][mt][2])), "r"(__float_as_uint(a[1][mt][3])),
                      "r"(__float_as_uint(b[nt][0])), "r"(__float_as_uint(b[nt][1])));
    };

    issue(0, 0);
    issue(1, GBK);
#pragma unroll
    for (int it = 0; it < DH / GBK; it++) {
        if (it < DH / GBK - 1)
            asm volatile("cp.async.wait_group 1;\n");
        else
            asm volatile("cp.async.wait_group 0;\n");
        __syncthreads();
        if (it + 2 < DH / GBK) issue((it + 2) % NSTAGE, (it + 2) * GBK);
        compute(it % NSTAGE);
    }

    // ---- fused attention scores (layers 1 & 2; fp32 accumulators) ----
    if (asrc) {
#pragma unroll
        for (int mt = 0; mt < 2; mt++) {
#pragma unroll
            for (int i = 0; i < 2; i++) {
                float s = 0.f, d = 0.f;
#pragma unroll
                for (int nt = 0; nt < 8; nt++) {
                    int col = colBlk + wn * 64 + nt * 8 + tg * 2;
                    s += c[mt][nt][i * 2] * asrc[col] + c[mt][nt][i * 2 + 1] * asrc[col + 1];
                    d += c[mt][nt][i * 2] * adst[col] + c[mt][nt][i * 2 + 1] * adst[col + 1];
                }
                s += __shfl_xor_sync(0xffffffffu, s, 1);
                s += __shfl_xor_sync(0xffffffffu, s, 2);
                d += __shfl_xor_sync(0xffffffffu, d, 1);
                d += __shfl_xor_sync(0xffffffffu, d, 2);
                int row = rowBlk + wm * 32 + mt * 16 + gid + i * 8;
                if (tg == 0 && row < M) {
                    atomicAdd(&as_out[row], s);
                    atomicAdd(&ad_out[row], d);
                }
            }
        }
    }

    // ---- store C (fp16 for aggregation path, fp32 otherwise) ----
#pragma unroll
    for (int mt = 0; mt < 2; mt++) {
#pragma unroll
        for (int i = 0; i < 2; i++) {
            int row = rowBlk + wm * 32 + mt * 16 + gid + i * 8;
            if (row >= M) continue;
#pragma unroll
            for (int nt = 0; nt < 8; nt++) {
                int col = colBlk + wn * 64 + nt * 8 + tg * 2;
                float v0 = c[mt][nt][i * 2 + 0];
                float v1 = c[mt][nt][i * 2 + 1];
                if (bias) { v0 += bias[col]; v1 += bias[col + 1]; }
                if (act) { v0 = fmaxf(v0, 0.f); v1 = fmaxf(v1, 0.f); }
                if (Ch) {
                    *(__half2*)(Ch + (size_t)row * DH + col) =
                        __floats2half2_rn(v0, v1);
                } else {
                    *(float2*)(C + (size_t)row * DH + col) = make_float2(v0, v1);
                }
            }
        }
    }
}

// ---------------- fused softmax + aggregation (warp per node, fp16 gather) ----------------
__global__ __launch_bounds__(256) void k_fusedagg(
    const __half* __restrict__ h, const float* __restrict__ bias,
    float* __restrict__ out, const float* __restrict__ gas,
    const float* __restrict__ gad, int N)
{
    int node = blockIdx.x * 8 + (threadIdx.x >> 5);
    if (node >= N) return;
    int lane = threadIdx.x & 31;
    int beg = g_rowptr[node], end = g_rowptr[node + 1];
    float adn = gad[node];

    // online softmax stats, lane-strided over edges
    float m = -1e30f, ssum = 0.f;
    for (int p = beg + lane; p < end; p += 32) {
        int s = g_perm[p];
        float v = gas[s] + adn;
        v = (v > 0.f) ? v : 0.2f * v;
        float mn = fmaxf(m, v);
        ssum = ssum * __expf(m - mn) + __expf(v - mn);
        m = mn;
    }
#pragma unroll
    for (int o = 16; o; o >>= 1) {
        float mo = __shfl_xor_sync(0xffffffffu, m, o);
        float so = __shfl_xor_sync(0xffffffffu, ssum, o);
        float mn = fmaxf(m, mo);
        ssum = ssum * __expf(m - mn) + so * __expf(mo - mn);
        m = mn;
    }
    float inv = 1.0f / (ssum + 1e-16f);

    // aggregate: lane owns 8 contiguous columns [lane*8, lane*8+8)
    float acc[8];
#pragma unroll
    for (int q = 0; q < 8; q++) acc[q] = 0.f;

    for (int c0 = beg; c0 < end; c0 += 32) {
        int p = c0 + lane;
        float al = 0.f;
        int s = 0;
        if (p < end) {
            s = g_perm[p];
            float v = gas[s] + adn;
            v = (v > 0.f) ? v : 0.2f * v;
            al = __expf(v - m) * inv;
        }
        int cnt = min(32, end - c0);
        for (int j = 0; j < cnt; j++) {
            float a = __shfl_sync(0xffffffffu, al, j);
            int ss = __shfl_sync(0xffffffffu, s, j);
            uint4 v = ((const uint4*)(h + (size_t)ss * DH))[lane];
            const __half2* hp = (const __half2*)&v;
            float2 f0 = __half22float2(hp[0]);
            float2 f1 = __half22float2(hp[1]);
            float2 f2 = __half22float2(hp[2]);
            float2 f3 = __half22float2(hp[3]);
            acc[0] += a * f0.x; acc[1] += a * f0.y;
            acc[2] += a * f1.x; acc[3] += a * f1.y;
            acc[4] += a * f2.x; acc[5] += a * f2.y;
            acc[6] += a * f3.x; acc[7] += a * f3.y;
        }
    }

    float4 b0 = ((const float4*)bias)[lane * 2];
    float4 b1 = ((const float4*)bias)[lane * 2 + 1];
    float4 o0, o1;
    o0.x = rnd_tf32(fmaxf(acc[0] + b0.x, 0.f)); o0.y = rnd_tf32(fmaxf(acc[1] + b0.y, 0.f));
    o0.z = rnd_tf32(fmaxf(acc[2] + b0.z, 0.f)); o0.w = rnd_tf32(fmaxf(acc[3] + b0.w, 0.f));
    o1.x = rnd_tf32(fmaxf(acc[4] + b1.x, 0.f)); o1.y = rnd_tf32(fmaxf(acc[5] + b1.y, 0.f));
    o1.z = rnd_tf32(fmaxf(acc[6] + b1.z, 0.f)); o1.w = rnd_tf32(fmaxf(acc[7] + b1.w, 0.f));
    float4* orow = (float4*)(out + (size_t)node * DH + lane * 8);
    orow[0] = o0;
    orow[1] = o1;
}

// ---------------- final head: out = tanh(x @ Wm2 + bm2), 256 -> 8 ----------------
__global__ __launch_bounds__(256) void k_mlp2(
    const float* __restrict__ x, const float* __restrict__ W,
    const float* __restrict__ b, float* __restrict__ out, int N)
{
    __shared__ float wT[8][256];
    for (int i = threadIdx.x; i < 2048; i += 256) {
        int k = i >> 3, o = i & 7;
        wT[o][k] = W[i];
    }
    __syncthreads();
    int node = blockIdx.x * 8 + (threadIdx.x >> 5);
    if (node >= N) return;
    int lane = threadIdx.x & 31;
    const float* row = x + (size_t)node * DH;
    float p[8] = {0, 0, 0, 0, 0, 0, 0, 0};
#pragma unroll
    for (int j = 0; j < 8; j++) {
        int k = lane + 32 * j;
        float xv = row[k];
#pragma unroll
        for (int o = 0; o < 8; o++) p[o] += xv * wT[o][k];
    }
#pragma unroll
    for (int o = 0; o < 8; o++)
#pragma unroll
        for (int off = 16; off; off >>= 1)
            p[o] += __shfl_xor_sync(0xffffffffu, p[o], off);
    if (lane < 8) {
        float v = p[0];
#pragma unroll
        for (int o = 1; o < 8; o++) if (lane == o) v = p[o];
        out[(size_t)node * AOUT + lane] = tanhf(v + b[lane]);
    }
}

// ---------------- launch ----------------
extern "C" void kernel_launch(void* const* d_in, const int* in_sizes, int n_in,
                              void* d_out, int out_size)
{
    const float* obs = (const float*)d_in[0];
    const int*   ei  = (const int*)d_in[1];
    const float* W1  = (const float*)d_in[2];
    const float* a1s = (const float*)d_in[3];
    const float* a1d = (const float*)d_in[4];
    const float* b1  = (const float*)d_in[5];
    const float* W2  = (const float*)d_in[6];
    const float* a2s = (const float*)d_in[7];
    const float* a2d = (const float*)d_in[8];
    const float* b2  = (const float*)d_in[9];
    const float* Wm1 = (const float*)d_in[10];
    const float* bm1 = (const float*)d_in[11];
    const float* Wm2 = (const float*)d_in[12];
    const float* bm2 = (const float*)d_in[13];
    float* out = (float*)d_out;

    const int N  = in_sizes[0] / DH;
    const int E  = in_sizes[1] / 2;

    float *bufA, *bufB, *bufC, *w1r, *w2r, *wm1r;
    float *as1, *ad1, *as2, *ad2;
    cudaGetSymbolAddress((void**)&bufA, g_bufA);
    cudaGetSymbolAddress((void**)&bufB, g_bufB);
    cudaGetSymbolAddress((void**)&bufC, g_bufC);
    cudaGetSymbolAddress((void**)&w1r,  g_w1r);
    cudaGetSymbolAddress((void**)&w2r,  g_w2r);
    cudaGetSymbolAddress((void**)&wm1r, g_wm1r);
    cudaGetSymbolAddress((void**)&as1,  g_as1);
    cudaGetSymbolAddress((void**)&ad1,  g_ad1);
    cudaGetSymbolAddress((void**)&as2,  g_as2);
    cudaGetSymbolAddress((void**)&ad2,  g_ad2);
    __half* bufAh = (__half*)bufA;     // fp16 view for the gather path

    cudaFuncSetAttribute(k_gemm_tf32, cudaFuncAttributeMaxDynamicSharedMemorySize, SMEM_GEMM);

    // side stream for scatter||gemm1 overlap (graph-capturable fork/join).
    // kernel_launch host code runs only a handful of times (correctness +
    // capture), so per-call creation is cheap and allocation-free.
    cudaStream_t s2;
    cudaEvent_t evScan, evScat;
    cudaStreamCreateWithFlags(&s2, cudaStreamNonBlocking);
    cudaEventCreateWithFlags(&evScan, cudaEventDisableTiming);
    cudaEventCreateWithFlags(&evScat, cudaEventDisableTiming);

    const int T = 256;
    dim3 gemmGrid(DH / GBN, (N + GBM - 1) / GBM);   // (2, 313)
    int nodeBlocks = (N + 7) / 8;
    int edgeBlocks = (E + T - 1) / T;
    int prepTotal  = 3 * 65536 + N;

    // 1: prep (round weights, zero cursors + score accumulators)
    k_prep<<<(prepTotal + T - 1) / T, T>>>(W1, W2, Wm1, N);
    // 2-3: CSR count (real edges only, int4) + scan (adds self-loops)
    k_count<<<(E / 4 + T - 1) / T, T>>>(ei, E);
    k_scan<<<1, 1024>>>(N);
    cudaEventRecord(evScan, 0);

    // scatter on side stream, overlapping gemm1
    cudaStreamWaitEvent(s2, evScan, 0);
    k_scatter<<<edgeBlocks, T, 0, s2>>>(ei, E);
    cudaEventRecord(evScat, s2);

    // 4: GAT layer-1 GEMM (raw obs, in-register tf32 round; fp16 h out)
    k_gemm_tf32<<<gemmGrid, 128, SMEM_GEMM>>>(obs, w1r, nullptr, bufAh, N,
                                              nullptr, 0, 1, a1s, a1d, as1, ad1);
    cudaStreamWaitEvent(0, evScat, 0);
    // 5: layer-1 softmax+aggregate (relu + b1, tf32-round for next GEMM)
    k_fusedagg<<<nodeBlocks, T>>>(bufAh, b1, bufB, as1, ad1, N);
    // 6-7: GAT layer 2
    k_gemm_tf32<<<gemmGrid, 128, SMEM_GEMM>>>(bufB, w2r, nullptr, bufAh, N,
                                              nullptr, 0, 0, a2s, a2d, as2, ad2);
    k_fusedagg<<<nodeBlocks, T>>>(bufAh, b2, bufB, as2, ad2, N);
    // 8: MLP layer 1 (relu + bm1, fp32 out for the head)
    k_gemm_tf32<<<gemmGrid, 128, SMEM_GEMM>>>(bufB, wm1r, bufC, nullptr, N,
                                              bm1, 1, 0, nullptr, nullptr, nullptr, nullptr);
    // 9: final head
    k_mlp2<<<nodeBlocks, T>>>(bufC, Wm2, bm2, out, N);
}

// round 7
// speedup vs baseline: 1.1446x; 1.0005x over previous
#include <cuda_runtime.h>
#include <cuda_fp16.h>
#include <math.h>

#define DH 256          // feature dim (D == H == 256)
#define AOUT 8
#define MAXN 20000
#define MAXE 320000
#define MAXT (MAXN + MAXE)

// ---------------- device scratch (no allocations allowed) ----------------
__device__ float    g_bufA[(size_t)MAXN * DH];   // fp16 view for gather path
__device__ float    g_bufB[(size_t)MAXN * DH];
__device__ float    g_bufC[(size_t)MAXN * DH];   // fp32 scratch (mlp1 out)
__device__ float    g_w1r[DH * DH];
__device__ float    g_w2r[DH * DH];
__device__ float    g_wm1r[DH * DH];
__device__ float    g_as1[MAXN];
__device__ float    g_ad1[MAXN];
__device__ float    g_as2[MAXN];
__device__ float    g_ad2[MAXN];
__device__ int      g_rowptr[MAXN + 1];
__device__ int      g_cursor[MAXN];
__device__ int      g_perm[MAXT];       // src node ids grouped by dst

__device__ __forceinline__ float rnd_tf32(float x) {
    unsigned u;
    asm("cvt.rna.tf32.f32 %0, %1;" : "=r"(u) : "f"(x));
    return __uint_as_float(u);
}

// ---------------- prep A: round weights to tf32, zero score accumulators ----------------
__global__ void k_prep_w(const float* __restrict__ W1,
                         const float* __restrict__ W2,
                         const float* __restrict__ Wm1, int N)
{
    int i = blockIdx.x * blockDim.x + threadIdx.x;
    if (i < 65536) {
        g_w1r[i] = rnd_tf32(W1[i]);
    } else if (i < 2 * 65536) {
        int j = i - 65536;
        g_w2r[j] = rnd_tf32(W2[j]);
    } else if (i < 3 * 65536) {
        int j = i - 2 * 65536;
        g_wm1r[j] = rnd_tf32(Wm1[j]);
    } else {
        int j = i - 3 * 65536;
        if (j < N) {
            g_as1[j] = 0.f; g_ad1[j] = 0.f;
            g_as2[j] = 0.f; g_ad2[j] = 0.f;
        }
    }
}

// ---------------- prep B: zero CSR cursors (side stream, heads CSR chain) ----------------
__global__ void k_prep_g(int N) {
    int i = blockIdx.x * blockDim.x + threadIdx.x;
    if (i < N) g_cursor[i] = 0;
}

// ---------------- CSR build (self-loops handled implicitly) ----------------
__global__ void k_count(const int* __restrict__ ei, int E) {
    int q = blockIdx.x * blockDim.x + threadIdx.x;
    if (q * 4 >= E) return;
    int4 d4 = *(const int4*)(ei + E + q * 4);
    atomicAdd(&g_cursor[d4.x], 1);
    atomicAdd(&g_cursor[d4.y], 1);
    atomicAdd(&g_cursor[d4.z], 1);
    atomicAdd(&g_cursor[d4.w], 1);
}

__global__ void k_scan(int N) {
    __shared__ int sh[1024];
    int tid = threadIdx.x;
    int per = (N + 1023) >> 10;
    int b0 = tid * per;
    int b1 = min(b0 + per, N);
    int loc = 0;
    for (int i = b0; i < b1; i++) loc += g_cursor[i] + 1;   // +1 self-loop
    sh[tid] = loc;
    __syncthreads();
#pragma unroll
    for (int o = 1; o < 1024; o <<= 1) {
        int t = (tid >= o) ? sh[tid - o] : 0;
        __syncthreads();
        sh[tid] += t;
        __syncthreads();
    }
    int run = (tid == 0) ? 0 : sh[tid - 1];
    for (int i = b0; i < b1; i++) {
        int c = g_cursor[i] + 1;
        g_rowptr[i] = run;
        g_perm[run] = i;            // self-loop at group head, no atomic
        g_cursor[i] = run + 1;
        run += c;
    }
    if (tid == 1023) g_rowptr[N] = sh[1023];
}

__global__ void k_scatter(const int* __restrict__ ei, int E) {
    int e = blockIdx.x * blockDim.x + threadIdx.x;
    if (e >= E) return;
    int s = ei[e], d = ei[E + e];
    int pos = atomicAdd(&g_cursor[d], 1);
    g_perm[pos] = s;
}

// ---------------- tf32 tensor-core GEMM: C[M,256] = A[M,256] @ B[256,256] ----------------
// CTA 64x128, BK=16, 4 warps (each 32x64), 3-stage cp.async, 4 CTAs/SM.
#define GBM 64
#define GBN 128
#define GBK 16
#define ASTR 20     // 16 + 4 pad (conflict-free mod 32)
#define BSTR 136    // 128 + 8 pad (conflict-free mod 32)
#define ASZ (GBM * ASTR)     // 1280
#define BSZ (GBK * BSTR)     // 2176
#define NSTAGE 3
#define SMEM_GEMM ((NSTAGE * (ASZ + BSZ)) * 4)   // 41472 bytes

__global__ __launch_bounds__(128, 4) void k_gemm_tf32(
    const float* __restrict__ A, const float* __restrict__ B,
    float* __restrict__ C, __half* __restrict__ Ch, int M,
    const float* __restrict__ bias, int act, int roundA,
    const float* __restrict__ asrc, const float* __restrict__ adst,
    float* as_out, float* ad_out)
{
    extern __shared__ float sm[];
    float* As = sm;                    // [NSTAGE][GBM][ASTR]
    float* Bs = sm + NSTAGE * ASZ;     // [NSTAGE][GBK][BSTR]

    const int tid = threadIdx.x;
    const int warpId = tid >> 5, lane = tid & 31;
    const int gid = lane >> 2, tg = lane & 3;
    const int wm = warpId >> 1, wn = warpId & 1;    // 2x2 warp grid
    const int rowBlk = blockIdx.y * GBM;
    const int colBlk = blockIdx.x * GBN;

    float c[2][8][4];
#pragma unroll
    for (int mt = 0; mt < 2; mt++)
#pragma unroll
        for (int nt = 0; nt < 8; nt++)
#pragma unroll
            for (int q = 0; q < 4; q++) c[mt][nt][q] = 0.f;

    auto issue = [&](int buf, int k0) {
#pragma unroll
        for (int i = 0; i < 2; i++) {           // A: 64x16 = 256 float4
            int f = tid + i * 128;
            int r = f >> 2, kq = (f & 3) << 2;
            int grow = rowBlk + r;
            const float* src = A + (size_t)grow * DH + k0 + kq;
            unsigned dst = (unsigned)__cvta_generic_to_shared(&As[buf * ASZ + r * ASTR + kq]);
            int sz = (grow < M) ? 16 : 0;
            asm volatile("cp.async.cg.shared.global [%0], [%1], 16, %2;\n"
                         :: "r"(dst), "l"(src), "r"(sz));
        }
#pragma unroll
        for (int i = 0; i < 4; i++) {           // B: 16x128 = 512 float4
            int f = tid + i * 128;
            int kr = f >> 5, nq = (f & 31) << 2;
            const float* src = B + (size_t)(k0 + kr) * DH + colBlk + nq;
            unsigned dst = (unsigned)__cvta_generic_to_shared(&Bs[buf * BSZ + kr * BSTR + nq]);
            asm volatile("cp.async.cg.shared.global [%0], [%1], 16;\n"
                         :: "r"(dst), "l"(src));
        }
        asm volatile("cp.async.commit_group;\n");
    };

    auto compute = [&](int buf) {
        float a[2][2][4];
#pragma unroll
        for (int ks = 0; ks < 2; ks++) {
            const int kk = ks * 8;
#pragma unroll
            for (int mt = 0; mt < 2; mt++) {
                const float* ab = &As[buf * ASZ + (wm * 32 + mt * 16 + gid) * ASTR + kk + tg];
                a[ks][mt][0] = ab[0];
                a[ks][mt][1] = ab[8 * ASTR];
                a[ks][mt][2] = ab[4];
                a[ks][mt][3] = ab[8 * ASTR + 4];
            }
        }
        if (roundA) {
#pragma unroll
            for (int ks = 0; ks < 2; ks++)
#pragma unroll
                for (int mt = 0; mt < 2; mt++)
#pragma unroll
                    for (int q = 0; q < 4; q++)
                        a[ks][mt][q] = rnd_tf32(a[ks][mt][q]);
        }
        float b[8][2];
#pragma unroll
        for (int nt = 0; nt < 8; nt++) {
            const float* bb = &Bs[buf * BSZ + tg * BSTR + wn * 64 + nt * 8 + gid];
            b[nt][0] = bb[0];
            b[nt][1] = bb[4 * BSTR];
        }
#pragma unroll
        for (int mt = 0; mt < 2; mt++)
#pragma unroll
            for (int nt = 0; nt < 8; nt++)
                asm volatile(
                    "mma.sync.aligned.m16n8k8.row.col.f32.tf32.tf32.f32 "
                    "{%0,%1,%2,%3}, {%4,%5,%6,%7}, {%8,%9}, {%0,%1,%2,%3};\n"
                    : "+f"(c[mt][nt][0]), "+f"(c[mt][nt][1]),
                      "+f"(c[mt][nt][2]), "+f"(c[mt][nt][3])
                    : "r"(__float_as_uint(a[0][mt][0])), "r"(__float_as_uint(a[0][mt][1])),
                      "r"(__float_as_uint(a[0][mt][2])), "r"(__float_as_uint(a[0][mt][3])),
                      "r"(__float_as_uint(b[nt][0])), "r"(__float_as_uint(b[nt][1])));
#pragma unroll
        for (int nt = 0; nt < 8; nt++) {
            const float* bb = &Bs[buf * BSZ + (8 + tg) * BSTR + wn * 64 + nt * 8 + gid];
            b[nt][0] = bb[0];
            b[nt][1] = bb[4 * BSTR];
        }
#pragma unroll
        for (int mt = 0; mt < 2; mt++)
#pragma unroll
            for (int nt = 0; nt < 8; nt++)
                asm volatile(
                    "mma.sync.aligned.m16n8k8.row.col.f32.tf32.tf32.f32 "
                    "{%0,%1,%2,%3}, {%4,%5,%6,%7}, {%8,%9}, {%0,%1,%2,%3};\n"
                    : "+f"(c[mt][nt][0]), "+f"(c[mt][nt][1]),
                      "+f"(c[mt][nt][2]), "+f"(c[mt][nt][3])
                    : "r"(__float_as_uint(a[1][mt][0])), "r"(__float_as_uint(a[1][mt][1])),
                      "r"(__float_as_uint(a[1][mt][2])), "r"(__float_as_uint(a[1][mt][3])),
                      "r"(__float_as_uint(b[nt][0])), "r"(__float_as_uint(b[nt][1])));
    };

    issue(0, 0);
    issue(1, GBK);
#pragma unroll
    for (int it = 0; it < DH / GBK; it++) {
        if (it < DH / GBK - 1)
            asm volatile("cp.async.wait_group 1;\n");
        else
            asm volatile("cp.async.wait_group 0;\n");
        __syncthreads();
        if (it + 2 < DH / GBK) issue((it + 2) % NSTAGE, (it + 2) * GBK);
        compute(it % NSTAGE);
    }

    // ---- fused attention scores (layers 1 & 2; fp32 accumulators) ----
    if (asrc) {
#pragma unroll
        for (int mt = 0; mt < 2; mt++) {
#pragma unroll
            for (int i = 0; i < 2; i++) {
                float s = 0.f, d = 0.f;
#pragma unroll
                for (int nt = 0; nt < 8; nt++) {
                    int col = colBlk + wn * 64 + nt * 8 + tg * 2;
                    s += c[mt][nt][i * 2] * asrc[col] + c[mt][nt][i * 2 + 1] * asrc[col + 1];
                    d += c[mt][nt][i * 2] * adst[col] + c[mt][nt][i * 2 + 1] * adst[col + 1];
                }
                s += __shfl_xor_sync(0xffffffffu, s, 1);
                s += __shfl_xor_sync(0xffffffffu, s, 2);
                d += __shfl_xor_sync(0xffffffffu, d, 1);
                d += __shfl_xor_sync(0xffffffffu, d, 2);
                int row = rowBlk + wm * 32 + mt * 16 + gid + i * 8;
                if (tg == 0 && row < M) {
                    atomicAdd(&as_out[row], s);
                    atomicAdd(&ad_out[row], d);
                }
            }
        }
    }

    // ---- store C (fp16 for aggregation path, fp32 otherwise) ----
#pragma unroll
    for (int mt = 0; mt < 2; mt++) {
#pragma unroll
        for (int i = 0; i < 2; i++) {
            int row = rowBlk + wm * 32 + mt * 16 + gid + i * 8;
            if (row >= M) continue;
#pragma unroll
            for (int nt = 0; nt < 8; nt++) {
                int col = colBlk + wn * 64 + nt * 8 + tg * 2;
                float v0 = c[mt][nt][i * 2 + 0];
                float v1 = c[mt][nt][i * 2 + 1];
                if (bias) { v0 += bias[col]; v1 += bias[col + 1]; }
                if (act) { v0 = fmaxf(v0, 0.f); v1 = fmaxf(v1, 0.f); }
                if (Ch) {
                    *(__half2*)(Ch + (size_t)row * DH + col) =
                        __floats2half2_rn(v0, v1);
                } else {
                    *(float2*)(C + (size_t)row * DH + col) = make_float2(v0, v1);
                }
            }
        }
    }
}

// ---------------- fused softmax + aggregation (warp per node, fp16 gather) ----------------
__global__ __launch_bounds__(256) void k_fusedagg(
    const __half* __restrict__ h, const float* __restrict__ bias,
    float* __restrict__ out, const float* __restrict__ gas,
    const float* __restrict__ gad, int N)
{
    int node = blockIdx.x * 8 + (threadIdx.x >> 5);
    if (node >= N) return;
    int lane = threadIdx.x & 31;
    int beg = g_rowptr[node], end = g_rowptr[node + 1];
    float adn = gad[node];

    float m = -1e30f, ssum = 0.f;
    for (int p = beg + lane; p < end; p += 32) {
        int s = g_perm[p];
        float v = gas[s] + adn;
        v = (v > 0.f) ? v : 0.2f * v;
        float mn = fmaxf(m, v);
        ssum = ssum * __expf(m - mn) + __expf(v - mn);
        m = mn;
    }
#pragma unroll
    for (int o = 16; o; o >>= 1) {
        float mo = __shfl_xor_sync(0xffffffffu, m, o);
        float so = __shfl_xor_sync(0xffffffffu, ssum, o);
        float mn = fmaxf(m, mo);
        ssum = ssum * __expf(m - mn) + so * __expf(mo - mn);
        m = mn;
    }
    float inv = 1.0f / (ssum + 1e-16f);

    float acc[8];
#pragma unroll
    for (int q = 0; q < 8; q++) acc[q] = 0.f;

    for (int c0 = beg; c0 < end; c0 += 32) {
        int p = c0 + lane;
        float al = 0.f;
        int s = 0;
        if (p < end) {
            s = g_perm[p];
            float v = gas[s] + adn;
            v = (v > 0.f) ? v : 0.2f * v;
            al = __expf(v - m) * inv;
        }
        int cnt = min(32, end - c0);
        for (int j = 0; j < cnt; j++) {
            float a = __shfl_sync(0xffffffffu, al, j);
            int ss = __shfl_sync(0xffffffffu, s, j);
            uint4 v = ((const uint4*)(h + (size_t)ss * DH))[lane];
            const __half2* hp = (const __half2*)&v;
            float2 f0 = __half22float2(hp[0]);
            float2 f1 = __half22float2(hp[1]);
            float2 f2 = __half22float2(hp[2]);
            float2 f3 = __half22float2(hp[3]);
            acc[0] += a * f0.x; acc[1] += a * f0.y;
            acc[2] += a * f1.x; acc[3] += a * f1.y;
            acc[4] += a * f2.x; acc[5] += a * f2.y;
            acc[6] += a * f3.x; acc[7] += a * f3.y;
        }
    }

    float4 b0 = ((const float4*)bias)[lane * 2];
    float4 b1 = ((const float4*)bias)[lane * 2 + 1];
    float4 o0, o1;
    o0.x = rnd_tf32(fmaxf(acc[0] + b0.x, 0.f)); o0.y = rnd_tf32(fmaxf(acc[1] + b0.y, 0.f));
    o0.z = rnd_tf32(fmaxf(acc[2] + b0.z, 0.f)); o0.w = rnd_tf32(fmaxf(acc[3] + b0.w, 0.f));
    o1.x = rnd_tf32(fmaxf(acc[4] + b1.x, 0.f)); o1.y = rnd_tf32(fmaxf(acc[5] + b1.y, 0.f));
    o1.z = rnd_tf32(fmaxf(acc[6] + b1.z, 0.f)); o1.w = rnd_tf32(fmaxf(acc[7] + b1.w, 0.f));
    float4* orow = (float4*)(out + (size_t)node * DH + lane * 8);
    orow[0] = o0;
    orow[1] = o1;
}

// ---------------- final head: out = tanh(x @ Wm2 + bm2), 256 -> 8 ----------------
__global__ __launch_bounds__(256) void k_mlp2(
    const float* __restrict__ x, const float* __restrict__ W,
    const float* __restrict__ b, float* __restrict__ out, int N)
{
    __shared__ float wT[8][256];
    for (int i = threadIdx.x; i < 2048; i += 256) {
        int k = i >> 3, o = i & 7;
        wT[o][k] = W[i];
    }
    __syncthreads();
    int node = blockIdx.x * 8 + (threadIdx.x >> 5);
    if (node >= N) return;
    int lane = threadIdx.x & 31;
    const float* row = x + (size_t)node * DH;
    float p[8] = {0, 0, 0, 0, 0, 0, 0, 0};
#pragma unroll
    for (int j = 0; j < 8; j++) {
        int k = lane + 32 * j;
        float xv = row[k];
#pragma unroll
        for (int o = 0; o < 8; o++) p[o] += xv * wT[o][k];
    }
#pragma unroll
    for (int o = 0; o < 8; o++)
#pragma unroll
        for (int off = 16; off; off >>= 1)
            p[o] += __shfl_xor_sync(0xffffffffu, p[o], off);
    if (lane < 8) {
        float v = p[0];
#pragma unroll
        for (int o = 1; o < 8; o++) if (lane == o) v = p[o];
        out[(size_t)node * AOUT + lane] = tanhf(v + b[lane]);
    }
}

// ---------------- launch ----------------
extern "C" void kernel_launch(void* const* d_in, const int* in_sizes, int n_in,
                              void* d_out, int out_size)
{
    const float* obs = (const float*)d_in[0];
    const int*   ei  = (const int*)d_in[1];
    const float* W1  = (const float*)d_in[2];
    const float* a1s = (const float*)d_in[3];
    const float* a1d = (const float*)d_in[4];
    const float* b1  = (const float*)d_in[5];
    const float* W2  = (const float*)d_in[6];
    const float* a2s = (const float*)d_in[7];
    const float* a2d = (const float*)d_in[8];
    const float* b2  = (const float*)d_in[9];
    const float* Wm1 = (const float*)d_in[10];
    const float* bm1 = (const float*)d_in[11];
    const float* Wm2 = (const float*)d_in[12];
    const float* bm2 = (const float*)d_in[13];
    float* out = (float*)d_out;

    const int N  = in_sizes[0] / DH;
    const int E  = in_sizes[1] / 2;

    float *bufA, *bufB, *bufC, *w1r, *w2r, *wm1r;
    float *as1, *ad1, *as2, *ad2;
    cudaGetSymbolAddress((void**)&bufA, g_bufA);
    cudaGetSymbolAddress((void**)&bufB, g_bufB);
    cudaGetSymbolAddress((void**)&bufC, g_bufC);
    cudaGetSymbolAddress((void**)&w1r,  g_w1r);
    cudaGetSymbolAddress((void**)&w2r,  g_w2r);
    cudaGetSymbolAddress((void**)&wm1r, g_wm1r);
    cudaGetSymbolAddress((void**)&as1,  g_as1);
    cudaGetSymbolAddress((void**)&ad1,  g_ad1);
    cudaGetSymbolAddress((void**)&as2,  g_as2);
    cudaGetSymbolAddress((void**)&ad2,  g_ad2);
    __half* bufAh = (__half*)bufA;     // fp16 view for the gather path

    cudaFuncSetAttribute(k_gemm_tf32, cudaFuncAttributeMaxDynamicSharedMemorySize, SMEM_GEMM);

    // side stream: whole CSR build runs concurrently with gemm1.
    cudaStream_t s2;
    cudaEvent_t evFork, evCsr;
    cudaStreamCreateWithFlags(&s2, cudaStreamNonBlocking);
    cudaEventCreateWithFlags(&evFork, cudaEventDisableTiming);
    cudaEventCreateWithFlags(&evCsr, cudaEventDisableTiming);

    const int T = 256;
    dim3 gemmGrid(DH / GBN, (N + GBM - 1) / GBM);   // (2, 313)
    int nodeBlocks = (N + 7) / 8;
    int edgeBlocks = (E + T - 1) / T;
    int prepWTotal = 3 * 65536 + N;

    // 1 (main): weight rounding + score-acc zeroing
    k_prep_w<<<(prepWTotal + T - 1) / T, T>>>(W1, W2, Wm1, N);
    cudaEventRecord(evFork, 0);

    // side chain: cursor zero -> count -> scan -> scatter (all independent of gemm1)
    cudaStreamWaitEvent(s2, evFork, 0);
    k_prep_g<<<(N + T - 1) / T, T, 0, s2>>>(N);                 // 2
    k_count<<<(E / 4 + T - 1) / T, T, 0, s2>>>(ei, E);          // 3

    // 4 (main): GAT layer-1 GEMM — profiled launch; overlaps CSR chain
    k_gemm_tf32<<<gemmGrid, 128, SMEM_GEMM>>>(obs, w1r, nullptr, bufAh, N,
                                              nullptr, 0, 1, a1s, a1d, as1, ad1);

    k_scan<<<1, 1024, 0, s2>>>(N);                              // 5
    k_scatter<<<edgeBlocks, T, 0, s2>>>(ei, E);                 // 6
    cudaEventRecord(evCsr, s2);
    cudaStreamWaitEvent(0, evCsr, 0);

    // 7: layer-1 softmax+aggregate (needs gemm1 + CSR)
    k_fusedagg<<<nodeBlocks, T>>>(bufAh, b1, bufB, as1, ad1, N);
    // 8-9: GAT layer 2
    k_gemm_tf32<<<gemmGrid, 128, SMEM_GEMM>>>(bufB, w2r, nullptr, bufAh, N,
                                              nullptr, 0, 0, a2s, a2d, as2, ad2);
    k_fusedagg<<<nodeBlocks, T>>>(bufAh, b2, bufB, as2, ad2, N);
    // 10: MLP layer 1 (relu + bm1, fp32 out for the head)
    k_gemm_tf32<<<gemmGrid, 128, SMEM_GEMM>>>(bufB, wm1r, bufC, nullptr, N,
                                              bm1, 1, 0, nullptr, nullptr, nullptr, nullptr);
    // 11: final head
    k_mlp2<<<nodeBlocks, T>>>(bufC, Wm2, bm2, out, N);
}

// round 8
// speedup vs baseline: 1.2640x; 1.1043x over previous
#include <cuda_runtime.h>
#include <cuda_fp16.h>
#include <math.h>

#define DH 256          // feature dim (D == H == 256)
#define AOUT 8
#define MAXN 20000
#define MAXE 320000
#define MAXT (MAXN + MAXE)

// ---------------- device scratch (no allocations allowed) ----------------
__device__ __half   g_obsh[(size_t)MAXN * DH];   // fp16 obs
__device__ __half   g_h1[(size_t)MAXN * DH];     // gemm outputs (fp16)
__device__ __half   g_h2[(size_t)MAXN * DH];
__device__ float    g_bufC[(size_t)MAXN * DH];   // mlp1 out (fp32)
__device__ __half   g_w1h[DH * DH];              // weights, fp16, TRANSPOSED [n][k]
__device__ __half   g_w2h[DH * DH];
__device__ __half   g_wm1h[DH * DH];
__device__ float    g_as1[MAXN];
__device__ float    g_ad1[MAXN];
__device__ float    g_as2[MAXN];
__device__ float    g_ad2[MAXN];
__device__ int      g_rowptr[MAXN + 1];
__device__ int      g_cursor[MAXN];
__device__ int      g_perm[MAXT];       // src node ids grouped by dst

// ---------------- prep A: weights -> fp16 transposed; zero accs + cursors ----------------
__global__ void k_prep_w(const float* __restrict__ W1,
                         const float* __restrict__ W2,
                         const float* __restrict__ Wm1, int N)
{
    int i = blockIdx.x * blockDim.x + threadIdx.x;
    if (i < 65536) {
        int n = i >> 8, k = i & 255;                 // write coalesced in [n][k]
        g_w1h[i] = __float2half(W1[k * DH + n]);
    } else if (i < 2 * 65536) {
        int j = i - 65536;
        int n = j >> 8, k = j & 255;
        g_w2h[j] = __float2half(W2[k * DH + n]);
    } else if (i < 3 * 65536) {
        int j = i - 2 * 65536;
        int n = j >> 8, k = j & 255;
        g_wm1h[j] = __float2half(Wm1[k * DH + n]);
    } else {
        int j = i - 3 * 65536;
        if (j < N) {
            g_cursor[j] = 0;
            g_as1[j] = 0.f; g_ad1[j] = 0.f;
            g_as2[j] = 0.f; g_ad2[j] = 0.f;
        }
    }
}

// ---------------- prep B: obs -> fp16 (vectorized 8/thread) ----------------
__global__ void k_prep_obs(const float* __restrict__ obs, int total8) {
    int i = blockIdx.x * blockDim.x + threadIdx.x;
    if (i >= total8) return;
    const float4* src = (const float4*)(obs) + i * 2;
    float4 v0 = src[0], v1 = src[1];
    __half2 h0 = __floats2half2_rn(v0.x, v0.y);
    __half2 h1 = __floats2half2_rn(v0.z, v0.w);
    __half2 h2 = __floats2half2_rn(v1.x, v1.y);
    __half2 h3 = __floats2half2_rn(v1.z, v1.w);
    uint4 pack;
    pack.x = *(unsigned*)&h0; pack.y = *(unsigned*)&h1;
    pack.z = *(unsigned*)&h2; pack.w = *(unsigned*)&h3;
    ((uint4*)g_obsh)[i] = pack;
}

// ---------------- CSR build (self-loops handled implicitly) ----------------
__global__ void k_count(const int* __restrict__ ei, int E) {
    int q = blockIdx.x * blockDim.x + threadIdx.x;
    if (q * 4 >= E) return;
    int4 d4 = *(const int4*)(ei + E + q * 4);
    atomicAdd(&g_cursor[d4.x], 1);
    atomicAdd(&g_cursor[d4.y], 1);
    atomicAdd(&g_cursor[d4.z], 1);
    atomicAdd(&g_cursor[d4.w], 1);
}

__global__ void k_scan(int N) {
    __shared__ int sh[1024];
    int tid = threadIdx.x;
    int per = (N + 1023) >> 10;
    int b0 = tid * per;
    int b1 = min(b0 + per, N);
    int loc = 0;
    for (int i = b0; i < b1; i++) loc += g_cursor[i] + 1;   // +1 self-loop
    sh[tid] = loc;
    __syncthreads();
#pragma unroll
    for (int o = 1; o < 1024; o <<= 1) {
        int t = (tid >= o) ? sh[tid - o] : 0;
        __syncthreads();
        sh[tid] += t;
        __syncthreads();
    }
    int run = (tid == 0) ? 0 : sh[tid - 1];
    for (int i = b0; i < b1; i++) {
        int c = g_cursor[i] + 1;
        g_rowptr[i] = run;
        g_perm[run] = i;            // self-loop at group head, no atomic
        g_cursor[i] = run + 1;
        run += c;
    }
    if (tid == 1023) g_rowptr[N] = sh[1023];
}

__global__ void k_scatter(const int* __restrict__ ei, int E) {
    int e = blockIdx.x * blockDim.x + threadIdx.x;
    if (e >= E) return;
    int s = ei[e], d = ei[E + e];
    int pos = atomicAdd(&g_cursor[d], 1);
    g_perm[pos] = s;
}

// ---------------- fp16 tensor-core GEMM: C[M,256] = A[M,256] @ B^T ----------------
// A fp16 [M][K] row-major; B fp16 [N][K] row-major (pre-transposed weights).
// CTA 64x128, BK=32, 4 warps (each 32x64), mma.m16n8k16, 3-stage cp.async.
#define GBM 64
#define GBN 128
#define GBK 32
#define ASTRH 40     // 32 + 8 pad halves (80B row; conflict-free)
#define BSTRH 40
#define ASZH (GBM * ASTRH)     // 2560 halves
#define BSZH (GBN * BSTRH)     // 5120 halves
#define NSTAGE 3
#define SMEM_GEMM (NSTAGE * (ASZH + BSZH) * 2)   // 46080 bytes

__global__ __launch_bounds__(128, 4) void k_gemm_f16(
    const __half* __restrict__ A, const __half* __restrict__ Bt,
    float* __restrict__ C, __half* __restrict__ Ch, int M,
    const float* __restrict__ bias, int act,
    const float* __restrict__ asrc, const float* __restrict__ adst,
    float* as_out, float* ad_out)
{
    extern __shared__ __half smh[];
    __half* As = smh;                      // [NSTAGE][GBM][ASTRH]
    __half* Bs = smh + NSTAGE * ASZH;      // [NSTAGE][GBN][BSTRH]

    const int tid = threadIdx.x;
    const int warpId = tid >> 5, lane = tid & 31;
    const int gid = lane >> 2, tg = lane & 3;
    const int wm = warpId >> 1, wn = warpId & 1;    // 2x2 warp grid
    const int rowBlk = blockIdx.y * GBM;
    const int colBlk = blockIdx.x * GBN;

    float c[2][8][4];
#pragma unroll
    for (int mt = 0; mt < 2; mt++)
#pragma unroll
        for (int nt = 0; nt < 8; nt++)
#pragma unroll
            for (int q = 0; q < 4; q++) c[mt][nt][q] = 0.f;

    auto issue = [&](int buf, int k0) {
#pragma unroll
        for (int i = 0; i < 2; i++) {           // A: 64 rows x 4 chunks(16B)
            int f = tid + i * 128;
            int r = f >> 2, ch = (f & 3) << 3;  // chunk offset in halves
            int grow = rowBlk + r;
            const __half* src = A + (size_t)grow * DH + k0 + ch;
            unsigned dst = (unsigned)__cvta_generic_to_shared(&As[buf * ASZH + r * ASTRH + ch]);
            int sz = (grow < M) ? 16 : 0;
            asm volatile("cp.async.cg.shared.global [%0], [%1], 16, %2;\n"
                         :: "r"(dst), "l"(src), "r"(sz));
        }
#pragma unroll
        for (int i = 0; i < 4; i++) {           // B: 128 rows(n) x 4 chunks
            int f = tid + i * 128;
            int n = f >> 2, ch = (f & 3) << 3;
            const __half* src = Bt + (size_t)(colBlk + n) * DH + k0 + ch;
            unsigned dst = (unsigned)__cvta_generic_to_shared(&Bs[buf * BSZH + n * BSTRH + ch]);
            asm volatile("cp.async.cg.shared.global [%0], [%1], 16;\n"
                         :: "r"(dst), "l"(src));
        }
        asm volatile("cp.async.commit_group;\n");
    };

    auto compute = [&](int buf) {
        // hoist A fragments for both k16 slices: 16 independent LDS.32
        unsigned a[2][2][4];
#pragma unroll
        for (int ks = 0; ks < 2; ks++) {
            const int kk = ks * 16;
#pragma unroll
            for (int mt = 0; mt < 2; mt++) {
                const __half* ab = &As[buf * ASZH + (wm * 32 + mt * 16 + gid) * ASTRH + kk + tg * 2];
                a[ks][mt][0] = *(const unsigned*)(ab);
                a[ks][mt][1] = *(const unsigned*)(ab + 8 * ASTRH);
                a[ks][mt][2] = *(const unsigned*)(ab + 8);
                a[ks][mt][3] = *(const unsigned*)(ab + 8 * ASTRH + 8);
            }
        }
#pragma unroll
        for (int ks = 0; ks < 2; ks++) {
            const int kk = ks * 16;
            unsigned b[8][2];
#pragma unroll
            for (int nt = 0; nt < 8; nt++) {
                const __half* bb = &Bs[buf * BSZH + (wn * 64 + nt * 8 + gid) * BSTRH + kk + tg * 2];
                b[nt][0] = *(const unsigned*)(bb);
                b[nt][1] = *(const unsigned*)(bb + 8);
            }
#pragma unroll
            for (int mt = 0; mt < 2; mt++)
#pragma unroll
                for (int nt = 0; nt < 8; nt++)
                    asm volatile(
                        "mma.sync.aligned.m16n8k16.row.col.f32.f16.f16.f32 "
                        "{%0,%1,%2,%3}, {%4,%5,%6,%7}, {%8,%9}, {%0,%1,%2,%3};\n"
                        : "+f"(c[mt][nt][0]), "+f"(c[mt][nt][1]),
                          "+f"(c[mt][nt][2]), "+f"(c[mt][nt][3])
                        : "r"(a[ks][mt][0]), "r"(a[ks][mt][1]),
                          "r"(a[ks][mt][2]), "r"(a[ks][mt][3]),
                          "r"(b[nt][0]), "r"(b[nt][1]));
        }
    };

    issue(0, 0);
    issue(1, GBK);
#pragma unroll
    for (int it = 0; it < DH / GBK; it++) {
        if (it < DH / GBK - 1)
            asm volatile("cp.async.wait_group 1;\n");
        else
            asm volatile("cp.async.wait_group 0;\n");
        __syncthreads();
        if (it + 2 < DH / GBK) issue((it + 2) % NSTAGE, (it + 2) * GBK);
        compute(it % NSTAGE);
    }

    // ---- fused attention scores (layers 1 & 2; fp32 accumulators) ----
    if (asrc) {
#pragma unroll
        for (int mt = 0; mt < 2; mt++) {
#pragma unroll
            for (int i = 0; i < 2; i++) {
                float s = 0.f, d = 0.f;
#pragma unroll
                for (int nt = 0; nt < 8; nt++) {
                    int col = colBlk + wn * 64 + nt * 8 + tg * 2;
                    s += c[mt][nt][i * 2] * asrc[col] + c[mt][nt][i * 2 + 1] * asrc[col + 1];
                    d += c[mt][nt][i * 2] * adst[col] + c[mt][nt][i * 2 + 1] * adst[col + 1];
                }
                s += __shfl_xor_sync(0xffffffffu, s, 1);
                s += __shfl_xor_sync(0xffffffffu, s, 2);
                d += __shfl_xor_sync(0xffffffffu, d, 1);
                d += __shfl_xor_sync(0xffffffffu, d, 2);
                int row = rowBlk + wm * 32 + mt * 16 + gid + i * 8;
                if (tg == 0 && row < M) {
                    atomicAdd(&as_out[row], s);
                    atomicAdd(&ad_out[row], d);
                }
            }
        }
    }

    // ---- store C (fp16 for aggregation path, fp32 otherwise) ----
#pragma unroll
    for (int mt = 0; mt < 2; mt++) {
#pragma unroll
        for (int i = 0; i < 2; i++) {
            int row = rowBlk + wm * 32 + mt * 16 + gid + i * 8;
            if (row >= M) continue;
#pragma unroll
            for (int nt = 0; nt < 8; nt++) {
                int col = colBlk + wn * 64 + nt * 8 + tg * 2;
                float v0 = c[mt][nt][i * 2 + 0];
                float v1 = c[mt][nt][i * 2 + 1];
                if (bias) { v0 += bias[col]; v1 += bias[col + 1]; }
                if (act) { v0 = fmaxf(v0, 0.f); v1 = fmaxf(v1, 0.f); }
                if (Ch) {
                    *(__half2*)(Ch + (size_t)row * DH + col) =
                        __floats2half2_rn(v0, v1);
                } else {
                    *(float2*)(C + (size_t)row * DH + col) = make_float2(v0, v1);
                }
            }
        }
    }
}

// ---------------- fused softmax + aggregation (warp per node, fp16 in/out) ----------------
__global__ __launch_bounds__(256) void k_fusedagg(
    const __half* __restrict__ h, const float* __restrict__ bias,
    __half* __restrict__ out, const float* __restrict__ gas,
    const float* __restrict__ gad, int N)
{
    int node = blockIdx.x * 8 + (threadIdx.x >> 5);
    if (node >= N) return;
    int lane = threadIdx.x & 31;
    int beg = g_rowptr[node], end = g_rowptr[node + 1];
    float adn = gad[node];

    float m = -1e30f, ssum = 0.f;
    for (int p = beg + lane; p < end; p += 32) {
        int s = g_perm[p];
        float v = gas[s] + adn;
        v = (v > 0.f) ? v : 0.2f * v;
        float mn = fmaxf(m, v);
        ssum = ssum * __expf(m - mn) + __expf(v - mn);
        m = mn;
    }
#pragma unroll
    for (int o = 16; o; o >>= 1) {
        float mo = __shfl_xor_sync(0xffffffffu, m, o);
        float so = __shfl_xor_sync(0xffffffffu, ssum, o);
        float mn = fmaxf(m, mo);
        ssum = ssum * __expf(m - mn) + so * __expf(mo - mn);
        m = mn;
    }
    float inv = 1.0f / (ssum + 1e-16f);

    float acc[8];
#pragma unroll
    for (int q = 0; q < 8; q++) acc[q] = 0.f;

    for (int c0 = beg; c0 < end; c0 += 32) {
        int p = c0 + lane;
        float al = 0.f;
        int s = 0;
        if (p < end) {
            s = g_perm[p];
            float v = gas[s] + adn;
            v = (v > 0.f) ? v : 0.2f * v;
            al = __expf(v - m) * inv;
        }
        int cnt = min(32, end - c0);
        for (int j = 0; j < cnt; j++) {
            float a = __shfl_sync(0xffffffffu, al, j);
            int ss = __shfl_sync(0xffffffffu, s, j);
            uint4 v = ((const uint4*)(h + (size_t)ss * DH))[lane];
            const __half2* hp = (const __half2*)&v;
            float2 f0 = __half22float2(hp[0]);
            float2 f1 = __half22float2(hp[1]);
            float2 f2 = __half22float2(hp[2]);
            float2 f3 = __half22float2(hp[3]);
            acc[0] += a * f0.x; acc[1] += a * f0.y;
            acc[2] += a * f1.x; acc[3] += a * f1.y;
            acc[4] += a * f2.x; acc[5] += a * f2.y;
            acc[6] += a * f3.x; acc[7] += a * f3.y;
        }
    }

    float4 b0 = ((const float4*)bias)[lane * 2];
    float4 b1 = ((const float4*)bias)[lane * 2 + 1];
    __half2 h0 = __floats2half2_rn(fmaxf(acc[0] + b0.x, 0.f), fmaxf(acc[1] + b0.y, 0.f));
    __half2 h1 = __floats2half2_rn(fmaxf(acc[2] + b0.z, 0.f), fmaxf(acc[3] + b0.w, 0.f));
    __half2 h2 = __floats2half2_rn(fmaxf(acc[4] + b1.x, 0.f), fmaxf(acc[5] + b1.y, 0.f));
    __half2 h3 = __floats2half2_rn(fmaxf(acc[6] + b1.z, 0.f), fmaxf(acc[7] + b1.w, 0.f));
    uint4 pack;
    pack.x = *(unsigned*)&h0; pack.y = *(unsigned*)&h1;
    pack.z = *(unsigned*)&h2; pack.w = *(unsigned*)&h3;
    *(uint4*)(out + (size_t)node * DH + lane * 8) = pack;
}

// ---------------- final head: out = tanh(x @ Wm2 + bm2), 256 -> 8 ----------------
__global__ __launch_bounds__(256) void k_mlp2(
    const float* __restrict__ x, const float* __restrict__ W,
    const float* __restrict__ b, float* __restrict__ out, int N)
{
    __shared__ float wT[8][256];
    for (int i = threadIdx.x; i < 2048; i += 256) {
        int k = i >> 3, o = i & 7;
        wT[o][k] = W[i];
    }
    __syncthreads();
    int node = blockIdx.x * 8 + (threadIdx.x >> 5);
    if (node >= N) return;
    int lane = threadIdx.x & 31;
    const float* row = x + (size_t)node * DH;
    float p[8] = {0, 0, 0, 0, 0, 0, 0, 0};
#pragma unroll
    for (int j = 0; j < 8; j++) {
        int k = lane + 32 * j;
        float xv = row[k];
#pragma unroll
        for (int o = 0; o < 8; o++) p[o] += xv * wT[o][k];
    }
#pragma unroll
    for (int o = 0; o < 8; o++)
#pragma unroll
        for (int off = 16; off; off >>= 1)
            p[o] += __shfl_xor_sync(0xffffffffu, p[o], off);
    if (lane < 8) {
        float v = p[0];
#pragma unroll
        for (int o = 1; o < 8; o++) if (lane == o) v = p[o];
        out[(size_t)node * AOUT + lane] = tanhf(v + b[lane]);
    }
}

// ---------------- launch ----------------
extern "C" void kernel_launch(void* const* d_in, const int* in_sizes, int n_in,
                              void* d_out, int out_size)
{
    const float* obs = (const float*)d_in[0];
    const int*   ei  = (const int*)d_in[1];
    const float* W1  = (const float*)d_in[2];
    const float* a1s = (const float*)d_in[3];
    const float* a1d = (const float*)d_in[4];
    const float* b1  = (const float*)d_in[5];
    const float* W2  = (const float*)d_in[6];
    const float* a2s = (const float*)d_in[7];
    const float* a2d = (const float*)d_in[8];
    const float* b2  = (const float*)d_in[9];
    const float* Wm1 = (const float*)d_in[10];
    const float* bm1 = (const float*)d_in[11];
    const float* Wm2 = (const float*)d_in[12];
    const float* bm2 = (const float*)d_in[13];
    float* out = (float*)d_out;

    const int N  = in_sizes[0] / DH;
    const int E  = in_sizes[1] / 2;

    __half *obsh, *h1, *h2, *w1h, *w2h, *wm1h;
    float *bufC, *as1, *ad1, *as2, *ad2;
    cudaGetSymbolAddress((void**)&obsh, g_obsh);
    cudaGetSymbolAddress((void**)&h1,   g_h1);
    cudaGetSymbolAddress((void**)&h2,   g_h2);
    cudaGetSymbolAddress((void**)&bufC, g_bufC);
    cudaGetSymbolAddress((void**)&w1h,  g_w1h);
    cudaGetSymbolAddress((void**)&w2h,  g_w2h);
    cudaGetSymbolAddress((void**)&wm1h, g_wm1h);
    cudaGetSymbolAddress((void**)&as1,  g_as1);
    cudaGetSymbolAddress((void**)&ad1,  g_ad1);
    cudaGetSymbolAddress((void**)&as2,  g_as2);
    cudaGetSymbolAddress((void**)&ad2,  g_ad2);

    cudaFuncSetAttribute(k_gemm_f16, cudaFuncAttributeMaxDynamicSharedMemorySize, SMEM_GEMM);

    cudaStream_t s2;
    cudaEvent_t evFork, evCsr;
    cudaStreamCreateWithFlags(&s2, cudaStreamNonBlocking);
    cudaEventCreateWithFlags(&evFork, cudaEventDisableTiming);
    cudaEventCreateWithFlags(&evCsr, cudaEventDisableTiming);

    const int T = 256;
    dim3 gemmGrid(DH / GBN, (N + GBM - 1) / GBM);   // (2, 313)
    int nodeBlocks = (N + 7) / 8;
    int edgeBlocks = (E + T - 1) / T;
    int prepWTotal = 3 * 65536 + N;
    int obs8 = N * DH / 8;

    // 1 (main): weight transpose->fp16 + zeroing (cursors, score accs)
    k_prep_w<<<(prepWTotal + T - 1) / T, T>>>(W1, W2, Wm1, N);
    cudaEventRecord(evFork, 0);
    // 2 (main): obs -> fp16
    k_prep_obs<<<(obs8 + T - 1) / T, T>>>(obs, obs8);
    // 3 (side): CSR count (needs cursor zeros from prep_w)
    cudaStreamWaitEvent(s2, evFork, 0);
    k_count<<<(E / 4 + T - 1) / T, T, 0, s2>>>(ei, E);
    // 4 (main): GAT layer-1 GEMM — profiled launch; overlaps CSR chain
    k_gemm_f16<<<gemmGrid, 128, SMEM_GEMM>>>(obsh, w1h, nullptr, h1, N,
                                             nullptr, 0, a1s, a1d, as1, ad1);
    // 5-6 (side): scan + scatter
    k_scan<<<1, 1024, 0, s2>>>(N);
    k_scatter<<<edgeBlocks, T, 0, s2>>>(ei, E);
    cudaEventRecord(evCsr, s2);
    cudaStreamWaitEvent(0, evCsr, 0);

    // 7: layer-1 softmax+aggregate (fp16 out -> gemm2 input)
    k_fusedagg<<<nodeBlocks, T>>>(h1, b1, h2, as1, ad1, N);
    // 8-9: GAT layer 2
    k_gemm_f16<<<gemmGrid, 128, SMEM_GEMM>>>(h2, w2h, nullptr, h1, N,
                                             nullptr, 0, a2s, a2d, as2, ad2);
    k_fusedagg<<<nodeBlocks, T>>>(h1, b2, h2, as2, ad2, N);
    // 10: MLP layer 1 (relu + bm1, fp32 out for the head)
    k_gemm_f16<<<gemmGrid, 128, SMEM_GEMM>>>(h2, wm1h, bufC, nullptr, N,
                                             bm1, 1, nullptr, nullptr, nullptr, nullptr);
    // 11: final head
    k_mlp2<<<nodeBlocks, T>>>(bufC, Wm2, bm2, out, N);
}